// round 14
// baseline (speedup 1.0000x reference)
#include <cuda_runtime.h>
#include <cstdint>

#define BSZ 4
#define CS  1024
#define PS  1024
#define DIN 1024
#define H   16
#define D   64
#define T   2048
#define HD  (H * D)
#define SCALEF 0.125f

// ---------------- scratch (static device globals; allocation-free) ----------
__device__ float g_kv [(size_t)BSZ * T * 2 * HD];   // [b*T+t][2048] k:0..1023 v:1024..2047 (tf32-rounded)
__device__ float g_q  [(size_t)BSZ * CS * HD];
__device__ float g_p  [(size_t)T * HD];
__device__ float g_pa [(size_t)H * BSZ * CS * T];   // [h][M][j] SHIFTED+SCALED position scores
__device__ float g_awv[(size_t)BSZ * CS * HD];      // tf32-rounded attention output

// tf32-rounded copies of GEMM sources
__device__ float r_input[(size_t)BSZ * CS * DIN];
__device__ float r_mem  [(size_t)BSZ * PS * DIN];
__device__ float r_pos  [(size_t)T * DIN];
__device__ float r_wkv  [(size_t)DIN * 2 * HD];
__device__ float r_wq   [(size_t)DIN * HD];
__device__ float r_wp   [(size_t)DIN * HD];
__device__ float r_wout [(size_t)HD * DIN];

// ---------------- tf32 helpers ----------------------------------------------
__device__ __forceinline__ uint32_t f2tf(float x) {
    uint32_t u;
    asm("cvt.rna.tf32.f32 %0, %1;" : "=r"(u) : "f"(x));
    return u;
}

#define MMA_TF32(c, a, b) \
    asm volatile("mma.sync.aligned.m16n8k8.row.col.f32.tf32.tf32.f32 " \
                 "{%0,%1,%2,%3},{%4,%5,%6,%7},{%8,%9},{%0,%1,%2,%3};" \
                 : "+f"(c[0]), "+f"(c[1]), "+f"(c[2]), "+f"(c[3]) \
                 : "r"(a[0]), "r"(a[1]), "r"(a[2]), "r"(a[3]), "r"(b[0]), "r"(b[1]))

__device__ __forceinline__ void cp16(uint32_t* smem_dst, const float* gmem_src) {
    uint32_t sa = (uint32_t)__cvta_generic_to_shared(smem_dst);
    asm volatile("cp.async.cg.shared.global [%0], [%1], 16;" :: "r"(sa), "l"(gmem_src));
}
#define CP_COMMIT asm volatile("cp.async.commit_group;")
#define CP_WAIT2  asm volatile("cp.async.wait_group 2;")
#define CP_WAIT1  asm volatile("cp.async.wait_group 1;")
#define CP_WAIT0  asm volatile("cp.async.wait_group 0;")

// ---------------- prep: fused tf32 rounding of all sources + pa zero fixup ---
__device__ __forceinline__ void r4cp(float* dst, const float* src, int i) {
    float4 v = *(const float4*)(src + (size_t)i * 4);
    uint4 r;
    r.x = f2tf(v.x); r.y = f2tf(v.y); r.z = f2tf(v.z); r.w = f2tf(v.w);
    *(uint4*)(dst + (size_t)i * 4) = r;
}

__global__ void prep(const float* __restrict__ in_, const float* __restrict__ mem_,
                     const float* __restrict__ pos_, const float* __restrict__ wkv_,
                     const float* __restrict__ wq_, const float* __restrict__ wp_,
                     const float* __restrict__ wo_)
{
    int i = blockIdx.x * 256 + threadIdx.x;
    const int N1 = 1048576, N2 = 524288, N3 = 262144;
    if (i < N1) { r4cp(r_input, in_, i); return; }  i -= N1;
    if (i < N1) { r4cp(r_mem,   mem_, i); return; } i -= N1;
    if (i < N2) { r4cp(r_pos,   pos_, i); return; } i -= N2;
    if (i < N2) { r4cp(r_wkv,   wkv_, i); return; } i -= N2;
    if (i < N3) { r4cp(r_wq,    wq_, i); return; }  i -= N3;
    if (i < N3) { r4cp(r_wp,    wp_, i); return; }  i -= N3;
    if (i < N3) { r4cp(r_wout,  wo_, i); return; }  i -= N3;
    // pa zero-cell fixup: sp=2049 -> j=M-2047 (2047<=M<=4094); sp=4098 -> j=M+2 (M<=2045)
    if (i < H * 4096) {
        int h = i >> 12, M = i & 4095;
        int j = -1;
        if (M >= 2047) { if (M <= 4094) j = M - 2047; }
        else if (M < 2046) j = M + 2;
        if (j >= 0) g_pa[((size_t)h * (BSZ * CS) + M) * T + j] = 0.f;
    }
}

// ---------------- GEMM: 128x128 tiles, 3-stage cp.async ring (depth 2) -------
#define AS_LD 36
#define BS_LD 136
#define STAGE_SZ (128 * AS_LD + 32 * BS_LD)   // 8960 words = 35840 B
#define MM_SMEM (3 * STAGE_SZ * 4)            // 107520 B -> still 2 blocks/SM

__device__ __forceinline__ void mma_chunk(float acc[4][4][4],
                                          const uint32_t* __restrict__ As,
                                          const uint32_t* __restrict__ Bs,
                                          int wm, int wn, int lane)
{
    int g = lane >> 2, t = lane & 3;
#pragma unroll
    for (int ks = 0; ks < 4; ks++) {
        uint32_t a[4][4];
#pragma unroll
        for (int mt = 0; mt < 4; mt++) {
            int row = wm * 64 + mt * 16 + g;
            int col = ks * 8 + t;
            a[mt][0] = As[row * AS_LD + col];
            a[mt][1] = As[(row + 8) * AS_LD + col];
            a[mt][2] = As[row * AS_LD + col + 4];
            a[mt][3] = As[(row + 8) * AS_LD + col + 4];
        }
        uint32_t b[4][2];
#pragma unroll
        for (int nt = 0; nt < 4; nt++) {
            int brow = ks * 8 + t;
            int bcol = wn * 32 + nt * 8 + g;
            b[nt][0] = Bs[brow * BS_LD + bcol];
            b[nt][1] = Bs[(brow + 4) * BS_LD + bcol];
        }
#pragma unroll
        for (int mt = 0; mt < 4; mt++)
#pragma unroll
            for (int nt = 0; nt < 4; nt++)
                MMA_TF32(acc[mt][nt], a[mt], b[nt]);
    }
}

template <bool RND>
__device__ __forceinline__ void store_C(float acc[4][4][4], float* C, int ldc,
                                        int m0, int n0, int wm, int wn, int lane)
{
    int g = lane >> 2, t = lane & 3;
#pragma unroll
    for (int mt = 0; mt < 4; mt++) {
#pragma unroll
        for (int nt = 0; nt < 4; nt++) {
            int row = m0 + wm * 64 + mt * 16 + g;
            int col = n0 + wn * 32 + nt * 8 + 2 * t;
            float v0 = acc[mt][nt][0], v1 = acc[mt][nt][1];
            float v2 = acc[mt][nt][2], v3 = acc[mt][nt][3];
            if (RND) {
                v0 = __uint_as_float(f2tf(v0)); v1 = __uint_as_float(f2tf(v1));
                v2 = __uint_as_float(f2tf(v2)); v3 = __uint_as_float(f2tf(v3));
            }
            *(float2*)(C + (size_t)row * ldc + col) = make_float2(v0, v1);
            *(float2*)(C + (size_t)(row + 8) * ldc + col) = make_float2(v2, v3);
        }
    }
}

__device__ __forceinline__ void stage_AB(uint32_t* As, uint32_t* Bs,
                                         const float* __restrict__ A, int lda,
                                         const float* __restrict__ B, int ldb,
                                         int m0, int n0, int k0, int tid)
{
#pragma unroll
    for (int i = 0; i < 4; i++) {
        int s = tid + i * 256;
        int row = s >> 3, kq = (s & 7) * 4;
        cp16(&As[row * AS_LD + kq], A + (size_t)(m0 + row) * lda + k0 + kq);
    }
#pragma unroll
    for (int i = 0; i < 4; i++) {
        int s = tid + i * 256;
        int k = s >> 5, n4 = (s & 31) * 4;
        cp16(&Bs[k * BS_LD + n4], B + (size_t)(k0 + k) * ldb + n0 + n4);
    }
}

__global__ __launch_bounds__(256, 2)
void mm_ca(const float* __restrict__ A, const float* __restrict__ B,
           float* __restrict__ C, int M, int N, int K)
{
    extern __shared__ uint32_t dsm[];
    int tid = threadIdx.x, lane = tid & 31, w = tid >> 5;
    int wm = w >> 2, wn = w & 3;
    int m0 = blockIdx.y * 128, n0 = blockIdx.x * 128;

    float acc[4][4][4];
#pragma unroll
    for (int i = 0; i < 4; i++)
#pragma unroll
        for (int j = 0; j < 4; j++)
#pragma unroll
            for (int r = 0; r < 4; r++) acc[i][j][r] = 0.f;

    uint32_t* SA[3] = { dsm, dsm + STAGE_SZ, dsm + 2 * STAGE_SZ };
    uint32_t* SB[3] = { dsm + 128 * AS_LD, dsm + STAGE_SZ + 128 * AS_LD,
                        dsm + 2 * STAGE_SZ + 128 * AS_LD };

    int NK = K >> 5;
#pragma unroll
    for (int c = 0; c < 3; c++) {
        stage_AB(SA[c], SB[c], A, K, B, N, m0, n0, c * 32, tid);
        CP_COMMIT;
    }
    CP_WAIT2;
    __syncthreads();

    for (int k = 0; k < NK; k++) {
        int cur = k % 3;
        mma_chunk(acc, SA[cur], SB[cur], wm, wn, lane);
        __syncthreads();
        if (k + 3 < NK)
            stage_AB(SA[cur], SB[cur], A, K, B, N, m0, n0, (k + 3) * 32, tid);
        CP_COMMIT;
        if (k + 2 < NK) { CP_WAIT2; } else if (k + 1 < NK) { CP_WAIT1; }
        __syncthreads();
    }
    store_C<false>(acc, C, N, m0, n0, wm, wn, lane);
}

__device__ __forceinline__ void stage_A_kv(uint32_t* As, int m0, int k0, int tid)
{
#pragma unroll
    for (int i = 0; i < 4; i++) {
        int s = tid + i * 256;
        int row = s >> 3, kq = (s & 7) * 4;
        int grow = m0 + row;
        int b = grow >> 11, tl = grow & (T - 1);
        const float* Arow = (tl < PS) ? (r_mem + (size_t)(b * PS + tl) * DIN)
                                      : (r_input + (size_t)(b * CS + tl - PS) * DIN);
        cp16(&As[row * AS_LD + kq], Arow + k0 + kq);
    }
}
__device__ __forceinline__ void stage_B_kv(uint32_t* Bs, int n0, int k0, int tid)
{
#pragma unroll
    for (int i = 0; i < 4; i++) {
        int s = tid + i * 256;
        int k = s >> 5, n4 = (s & 31) * 4;
        cp16(&Bs[k * BS_LD + n4], r_wkv + (size_t)(k0 + k) * (2 * HD) + n0 + n4);
    }
}

__global__ __launch_bounds__(256, 2)
void mm_ca_kv()
{
    extern __shared__ uint32_t dsm[];
    int tid = threadIdx.x, lane = tid & 31, w = tid >> 5;
    int wm = w >> 2, wn = w & 3;
    int m0 = blockIdx.y * 128, n0 = blockIdx.x * 128;

    float acc[4][4][4];
#pragma unroll
    for (int i = 0; i < 4; i++)
#pragma unroll
        for (int j = 0; j < 4; j++)
#pragma unroll
            for (int r = 0; r < 4; r++) acc[i][j][r] = 0.f;

    uint32_t* SA[3] = { dsm, dsm + STAGE_SZ, dsm + 2 * STAGE_SZ };
    uint32_t* SB[3] = { dsm + 128 * AS_LD, dsm + STAGE_SZ + 128 * AS_LD,
                        dsm + 2 * STAGE_SZ + 128 * AS_LD };

    const int NK = DIN >> 5;
#pragma unroll
    for (int c = 0; c < 3; c++) {
        stage_A_kv(SA[c], m0, c * 32, tid);
        stage_B_kv(SB[c], n0, c * 32, tid);
        CP_COMMIT;
    }
    CP_WAIT2;
    __syncthreads();

    for (int k = 0; k < NK; k++) {
        int cur = k % 3;
        mma_chunk(acc, SA[cur], SB[cur], wm, wn, lane);
        __syncthreads();
        if (k + 3 < NK) {
            stage_A_kv(SA[cur], m0, (k + 3) * 32, tid);
            stage_B_kv(SB[cur], n0, (k + 3) * 32, tid);
        }
        CP_COMMIT;
        if (k + 2 < NK) { CP_WAIT2; } else if (k + 1 < NK) { CP_WAIT1; }
        __syncthreads();
    }
    // rounded store -> attn can cp.async K/V raw (bit-identical to f2tf at load)
    store_C<true>(acc, g_kv, 2 * HD, m0, n0, wm, wn, lane);
}

// ---------------- position-attn GEMM with SHIFT-ON-WRITE epilogue ------------
#define PA_LD 68
#define PA_SMEM (2 * 128 * PA_LD * 4)   // 69632 B

__device__ __forceinline__ void scatter_pa(float* __restrict__ Ch, int rp, int cp, float val)
{
    int s = rp + cp;
    int a = (s <= 2046) ? 2 : ((s <= 4094) ? 1 : 0);
    int M = rp - a;
    if (M < 0) return;
    int j = s + 1 - 4096 + (a << 11);
    if (j > (M & (CS - 1)) + PS) return;     // masked cell — overwritten by -1e30 at read
    Ch[(size_t)M * T + j] = val * SCALEF;
}

__global__ __launch_bounds__(256, 2)
void mm_pa2(const float* __restrict__ vvec)
{
    extern __shared__ uint32_t psm[];
    uint32_t* As = psm;                  // 128 x 68 (q+v rows, K-major tf32)
    uint32_t* Bs = psm + 128 * PA_LD;    // 128 x 68 (p rows,   K-major tf32)

    int tid = threadIdx.x, lane = tid & 31, w = tid >> 5;
    int wm = w >> 2, wn = w & 3;
    int h = blockIdx.z;
    int m0 = blockIdx.y * 128, n0 = blockIdx.x * 128;
    int g = lane >> 2, t = lane & 3;

#pragma unroll
    for (int l = 0; l < 8; l++) {
        int idx = tid + l * 256;
        int r = idx >> 4, kq = (idx & 15) * 4;
        float4 a = *(const float4*)(g_q + (size_t)(m0 + r) * HD + h * D + kq);
        float4 vx = *(const float4*)(vvec + h * D + kq);
        uint4 ua;
        ua.x = f2tf(a.x + vx.x); ua.y = f2tf(a.y + vx.y);
        ua.z = f2tf(a.z + vx.z); ua.w = f2tf(a.w + vx.w);
        *(uint4*)&As[r * PA_LD + kq] = ua;
        float4 p4 = *(const float4*)(g_p + (size_t)(n0 + r) * HD + h * D + kq);
        uint4 ub;
        ub.x = f2tf(p4.x); ub.y = f2tf(p4.y); ub.z = f2tf(p4.z); ub.w = f2tf(p4.w);
        *(uint4*)&Bs[r * PA_LD + kq] = ub;
    }
    __syncthreads();

    float acc[4][4][4];
#pragma unroll
    for (int i = 0; i < 4; i++)
#pragma unroll
        for (int j = 0; j < 4; j++)
#pragma unroll
            for (int r = 0; r < 4; r++) acc[i][j][r] = 0.f;

#pragma unroll
    for (int ks = 0; ks < 8; ks++) {
        uint32_t a[4][4];
#pragma unroll
        for (int mt = 0; mt < 4; mt++) {
            int row = wm * 64 + mt * 16 + g;
            int col = ks * 8 + t;
            a[mt][0] = As[row * PA_LD + col];
            a[mt][1] = As[(row + 8) * PA_LD + col];
            a[mt][2] = As[row * PA_LD + col + 4];
            a[mt][3] = As[(row + 8) * PA_LD + col + 4];
        }
        uint32_t b[4][2];
#pragma unroll
        for (int nt = 0; nt < 4; nt++) {
            int bcol = wn * 32 + nt * 8 + g;
            b[nt][0] = Bs[bcol * PA_LD + ks * 8 + t];
            b[nt][1] = Bs[bcol * PA_LD + ks * 8 + t + 4];
        }
#pragma unroll
        for (int mt = 0; mt < 4; mt++)
#pragma unroll
            for (int nt = 0; nt < 4; nt++)
                MMA_TF32(acc[mt][nt], a[mt], b[nt]);
    }

    float* Ch = g_pa + (size_t)h * (BSZ * CS) * T;
#pragma unroll
    for (int mt = 0; mt < 4; mt++) {
#pragma unroll
        for (int nt = 0; nt < 4; nt++) {
            int row0 = m0 + wm * 64 + mt * 16 + g;
            int col0 = n0 + wn * 32 + nt * 8 + 2 * t;
            scatter_pa(Ch, row0,     col0,     acc[mt][nt][0]);
            scatter_pa(Ch, row0,     col0 + 1, acc[mt][nt][1]);
            scatter_pa(Ch, row0 + 8, col0,     acc[mt][nt][2]);
            scatter_pa(Ch, row0 + 8, col0 + 1, acc[mt][nt][3]);
        }
    }
}

// ---------------- flash attention: cp.async K/V + hoisted pos prefetch --------
#define AT_LD 68
#define ATT_SMEM ((2 * 2 * 64 * AT_LD + 128 * AT_LD) * 4)   // 104448 B

__device__ __forceinline__ void stage_kv_tile(uint32_t* buf, int b, int h, int j0, int tid)
{
#pragma unroll
    for (int l = 0; l < 4; l++) {
        int idx = tid + l * 256;
        int r = idx >> 4, q = idx & 15;
        const float* src = g_kv + (size_t)(b * T + j0 + r) * (2 * HD) + h * D + q * 4;
        cp16(buf + r * AT_LD + q * 4, src);                   // K
        cp16(buf + 64 * AT_LD + r * AT_LD + q * 4, src + HD); // V
    }
}

__global__ __launch_bounds__(256, 2)
void attn_tc(const float* __restrict__ u)
{
    extern __shared__ uint32_t sm[];
    uint32_t* Ps = sm + 2 * 2 * 64 * AT_LD;   // 128 x 68 (Q staging, then P)

    int tid = threadIdx.x, lane = tid & 31, w = tid >> 5;
    int b = blockIdx.z, h = blockIdx.y;
    int q0 = (int)(gridDim.x - 1 - blockIdx.x) * 128;
    int g = lane >> 2, t = lane & 3;

    // Q(+u), pre-scaled by SCALEF (exact power of 2), tf32
    for (int i = tid; i < 128 * 16; i += 256) {
        int r = i >> 4, d4 = (i & 15) * 4;
        float4 qv = *(const float4*)(g_q + (size_t)(b * CS + q0 + r) * HD + h * D + d4);
        float4 uv = *(const float4*)(u + h * D + d4);
        Ps[r * AT_LD + d4 + 0] = f2tf((qv.x + uv.x) * SCALEF);
        Ps[r * AT_LD + d4 + 1] = f2tf((qv.y + uv.y) * SCALEF);
        Ps[r * AT_LD + d4 + 2] = f2tf((qv.z + uv.z) * SCALEF);
        Ps[r * AT_LD + d4 + 3] = f2tf((qv.w + uv.w) * SCALEF);
    }
    __syncthreads();

    uint32_t qf[8][4];
    {
        int r0 = w * 16 + g;
#pragma unroll
        for (int ks = 0; ks < 8; ks++) {
            qf[ks][0] = Ps[r0 * AT_LD + ks * 8 + t];
            qf[ks][1] = Ps[(r0 + 8) * AT_LD + ks * 8 + t];
            qf[ks][2] = Ps[r0 * AT_LD + ks * 8 + t + 4];
            qf[ks][3] = Ps[(r0 + 8) * AT_LD + ks * 8 + t + 4];
        }
    }

    float of[8][4];
#pragma unroll
    for (int nt = 0; nt < 8; nt++)
#pragma unroll
        for (int r = 0; r < 4; r++) of[nt][r] = 0.f;
    float m0r = -1e30f, m1r = -1e30f, l0 = 0.f, l1 = 0.f;

    int iq_g = q0 + w * 16 + g;
    int Mrow_g = b * CS + iq_g;
    int pr0 = (w * 16 + g) * AT_LD, pr8 = (w * 16 + g + 8) * AT_LD;
    int ntiles = q0 / 64 + 18;

    const float* pab0 = g_pa + ((size_t)h * (BSZ * CS) + Mrow_g) * T;
    const float* pab8 = pab0 + (size_t)8 * T;

    stage_kv_tile(sm, b, h, 0, tid);   // tile 0 -> buf 0
    CP_COMMIT;

    for (int tt = 0; tt < ntiles; tt++) {
        int cur = tt & 1;
        uint32_t* Kc = sm + cur * (2 * 64 * AT_LD);
        uint32_t* Vc = Kc + 64 * AT_LD;
        int j0 = tt * 64;

        __syncthreads();   // all warps done reading buf[1-cur] (iter tt-1)
        if (tt + 1 < ntiles) {
            stage_kv_tile(sm + (1 - cur) * (2 * 64 * AT_LD), b, h, j0 + 64, tid);
            CP_COMMIT;
        }

        // hoisted pos prefetch: issue gmem loads BEFORE cp wait + S MMAs
        float2 pp0[8], pp8[8];
#pragma unroll
        for (int nt = 0; nt < 8; nt++) {
            int j = j0 + nt * 8 + 2 * t;
            pp0[nt] = __ldg((const float2*)(pab0 + j));
            pp8[nt] = __ldg((const float2*)(pab8 + j));
        }

        if (tt + 1 < ntiles) { CP_WAIT1; } else { CP_WAIT0; }
        __syncthreads();

        // S = (Q+u)*SCALE @ K^T
        float sf[8][4];
#pragma unroll
        for (int nt = 0; nt < 8; nt++) {
            sf[nt][0] = sf[nt][1] = sf[nt][2] = sf[nt][3] = 0.f;
#pragma unroll
            for (int ks = 0; ks < 8; ks++) {
                uint32_t bb[2];
                bb[0] = Kc[(nt * 8 + g) * AT_LD + ks * 8 + t];
                bb[1] = Kc[(nt * 8 + g) * AT_LD + ks * 8 + t + 4];
                MMA_TF32(sf[nt], qf[ks], bb);
            }
        }

        // add prefetched pre-shifted pre-scaled pos + mask
        bool need_mask = (tt >= ntiles - 2);
#pragma unroll
        for (int nt = 0; nt < 8; nt++) {
            int j = j0 + nt * 8 + 2 * t;
            sf[nt][0] += pp0[nt].x; sf[nt][1] += pp0[nt].y;
            sf[nt][2] += pp8[nt].x; sf[nt][3] += pp8[nt].y;
            if (need_mask) {
                int lim0 = iq_g + PS, lim1 = lim0 + 8;
                if (j     > lim0) sf[nt][0] = -1e30f;
                if (j + 1 > lim0) sf[nt][1] = -1e30f;
                if (j     > lim1) sf[nt][2] = -1e30f;
                if (j + 1 > lim1) sf[nt][3] = -1e30f;
            }
        }

        // online softmax
        float tm0 = -1e30f, tm1 = -1e30f;
#pragma unroll
        for (int nt = 0; nt < 8; nt++) {
            tm0 = fmaxf(tm0, fmaxf(sf[nt][0], sf[nt][1]));
            tm1 = fmaxf(tm1, fmaxf(sf[nt][2], sf[nt][3]));
        }
        tm0 = fmaxf(tm0, __shfl_xor_sync(0xffffffffu, tm0, 1));
        tm0 = fmaxf(tm0, __shfl_xor_sync(0xffffffffu, tm0, 2));
        tm1 = fmaxf(tm1, __shfl_xor_sync(0xffffffffu, tm1, 1));
        tm1 = fmaxf(tm1, __shfl_xor_sync(0xffffffffu, tm1, 2));
        float nm0 = fmaxf(m0r, tm0), nm1 = fmaxf(m1r, tm1);
        float cr0 = __expf(m0r - nm0), cr1 = __expf(m1r - nm1);

        float ps0 = 0.f, ps1 = 0.f;
#pragma unroll
        for (int nt = 0; nt < 8; nt++) {
            float e0 = __expf(sf[nt][0] - nm0);
            float e1 = __expf(sf[nt][1] - nm0);
            float e2 = __expf(sf[nt][2] - nm1);
            float e3 = __expf(sf[nt][3] - nm1);
            int col = nt * 8 + 2 * t;
            Ps[pr0 + col]     = f2tf(e0);
            Ps[pr0 + col + 1] = f2tf(e1);
            Ps[pr8 + col]     = f2tf(e2);
            Ps[pr8 + col + 1] = f2tf(e3);
            ps0 += e0 + e1;
            ps1 += e2 + e3;
        }
        ps0 += __shfl_xor_sync(0xffffffffu, ps0, 1);
        ps0 += __shfl_xor_sync(0xffffffffu, ps0, 2);
        ps1 += __shfl_xor_sync(0xffffffffu, ps1, 1);
        ps1 += __shfl_xor_sync(0xffffffffu, ps1, 2);
        l0 = l0 * cr0 + ps0;
        l1 = l1 * cr1 + ps1;
        m0r = nm0; m1r = nm1;
#pragma unroll
        for (int nt = 0; nt < 8; nt++) {
            of[nt][0] *= cr0; of[nt][1] *= cr0;
            of[nt][2] *= cr1; of[nt][3] *= cr1;
        }
        __syncwarp();

        uint32_t af[8][4];
#pragma unroll
        for (int ks = 0; ks < 8; ks++) {
            af[ks][0] = Ps[pr0 + ks * 8 + t];
            af[ks][1] = Ps[pr8 + ks * 8 + t];
            af[ks][2] = Ps[pr0 + ks * 8 + t + 4];
            af[ks][3] = Ps[pr8 + ks * 8 + t + 4];
        }
#pragma unroll
        for (int nt = 0; nt < 8; nt++) {
#pragma unroll
            for (int ks = 0; ks < 8; ks++) {
                uint32_t bb[2];
                bb[0] = Vc[(ks * 8 + t) * AT_LD + nt * 8 + g];
                bb[1] = Vc[(ks * 8 + t + 4) * AT_LD + nt * 8 + g];
                MMA_TF32(of[nt], af[ks], bb);
            }
        }
        __syncwarp();
    }

    float i0 = 1.f / l0, i1 = 1.f / l1;
    int orow = b * CS + q0 + w * 16 + g;
#pragma unroll
    for (int nt = 0; nt < 8; nt++) {
        int col = h * D + nt * 8 + 2 * t;
        float2 v0 = make_float2(__uint_as_float(f2tf(of[nt][0] * i0)),
                                __uint_as_float(f2tf(of[nt][1] * i0)));
        float2 v1 = make_float2(__uint_as_float(f2tf(of[nt][2] * i1)),
                                __uint_as_float(f2tf(of[nt][3] * i1)));
        *(float2*)(g_awv + (size_t)orow * HD + col) = v0;
        *(float2*)(g_awv + (size_t)(orow + 8) * HD + col) = v1;
    }
}

// ---------------- launch -------------------------------------------------------
extern "C" void kernel_launch(void* const* d_in, const int* in_sizes, int n_in,
                              void* d_out, int out_size)
{
    const float* input  = (const float*)d_in[0];
    const float* pos    = (const float*)d_in[1];
    const float* memory = (const float*)d_in[2];
    const float* u      = (const float*)d_in[3];
    const float* v      = (const float*)d_in[4];
    const float* Wkv    = (const float*)d_in[5];
    const float* Wq     = (const float*)d_in[6];
    const float* Wp     = (const float*)d_in[7];
    const float* Wout   = (const float*)d_in[8];
    float* out = (float*)d_out;

    float *pq, *pp, *pawv;
    float *pri, *prp, *prq, *prwp, *prwo;
    cudaGetSymbolAddress((void**)&pq,   g_q);
    cudaGetSymbolAddress((void**)&pp,   g_p);
    cudaGetSymbolAddress((void**)&pawv, g_awv);
    cudaGetSymbolAddress((void**)&pri,  r_input);
    cudaGetSymbolAddress((void**)&prp,  r_pos);
    cudaGetSymbolAddress((void**)&prq,  r_wq);
    cudaGetSymbolAddress((void**)&prwp, r_wp);
    cudaGetSymbolAddress((void**)&prwo, r_wout);

    cudaFuncSetAttribute(mm_ca,    cudaFuncAttributeMaxDynamicSharedMemorySize, MM_SMEM);
    cudaFuncSetAttribute(mm_ca_kv, cudaFuncAttributeMaxDynamicSharedMemorySize, MM_SMEM);
    cudaFuncSetAttribute(mm_pa2,   cudaFuncAttributeMaxDynamicSharedMemorySize, PA_SMEM);
    cudaFuncSetAttribute(attn_tc,  cudaFuncAttributeMaxDynamicSharedMemorySize, ATT_SMEM);

    // launch 0: fused tf32 pre-round of all sources + pa zero-cell fixup
    prep<<<15616, 256>>>(input, memory, pos, Wkv, Wq, Wp, Wout);
    // launch 1: kv = [memory; input] @ W_kv   (8192 x 2048 x 1024), rounded store
    mm_ca_kv<<<dim3(16, 64), 256, MM_SMEM>>>();
    // launch 2: q = input @ W_q               (4096 x 1024 x 1024)
    mm_ca<<<dim3(8, 32), 256, MM_SMEM>>>(pri, prq, pq, BSZ * CS, HD, DIN);
    // launch 3: p = pos_embs @ W_p            (2048 x 1024 x 1024)
    mm_ca<<<dim3(8, 16), 256, MM_SMEM>>>(prp, prwp, pp, T, HD, DIN);
    // launch 4: pos-attn per head, shift-on-write  (16 x 4096 x 2048 x 64)
    mm_pa2<<<dim3(16, 32, H), 256, PA_SMEM>>>(v);
    // launch 5: flash attention
    attn_tc<<<dim3(8, H, BSZ), 256, ATT_SMEM>>>(u);
    // launch 6: out = awv @ W_out             (4096 x 1024 x 1024)
    mm_ca<<<dim3(8, 32), 256, MM_SMEM>>>(pawv, prwo, out, BSZ * CS, DIN, HD);
}

// round 15
// speedup vs baseline: 1.0537x; 1.0537x over previous
#include <cuda_runtime.h>
#include <cstdint>

#define BSZ 4
#define CS  1024
#define PS  1024
#define DIN 1024
#define H   16
#define D   64
#define T   2048
#define HD  (H * D)
#define SCALEF 0.125f

// ---------------- scratch (static device globals; allocation-free) ----------
__device__ float g_kv [(size_t)BSZ * T * 2 * HD];   // [b*T+t][2048] k:0..1023 v:1024..2047 (tf32-rounded)
__device__ float g_q  [(size_t)BSZ * CS * HD];
__device__ float g_p  [(size_t)T * HD];
__device__ float g_pa [(size_t)H * BSZ * CS * T];   // [h][M][j] SHIFTED+SCALED position scores
__device__ float g_awv[(size_t)BSZ * CS * HD];      // tf32-rounded attention output

// tf32-rounded copies of GEMM sources
__device__ float r_input[(size_t)BSZ * CS * DIN];
__device__ float r_mem  [(size_t)BSZ * PS * DIN];
__device__ float r_pos  [(size_t)T * DIN];
__device__ float r_wkv  [(size_t)DIN * 2 * HD];
__device__ float r_wq   [(size_t)DIN * HD];
__device__ float r_wp   [(size_t)DIN * HD];
__device__ float r_wout [(size_t)HD * DIN];

// ---------------- tf32 helpers ----------------------------------------------
__device__ __forceinline__ uint32_t f2tf(float x) {
    uint32_t u;
    asm("cvt.rna.tf32.f32 %0, %1;" : "=r"(u) : "f"(x));
    return u;
}

#define MMA_TF32(c, a, b) \
    asm volatile("mma.sync.aligned.m16n8k8.row.col.f32.tf32.tf32.f32 " \
                 "{%0,%1,%2,%3},{%4,%5,%6,%7},{%8,%9},{%0,%1,%2,%3};" \
                 : "+f"(c[0]), "+f"(c[1]), "+f"(c[2]), "+f"(c[3]) \
                 : "r"(a[0]), "r"(a[1]), "r"(a[2]), "r"(a[3]), "r"(b[0]), "r"(b[1]))

__device__ __forceinline__ void cp16(uint32_t* smem_dst, const float* gmem_src) {
    uint32_t sa = (uint32_t)__cvta_generic_to_shared(smem_dst);
    asm volatile("cp.async.cg.shared.global [%0], [%1], 16;" :: "r"(sa), "l"(gmem_src));
}
#define CP_COMMIT asm volatile("cp.async.commit_group;")
#define CP_WAIT1  asm volatile("cp.async.wait_group 1;")
#define CP_WAIT0  asm volatile("cp.async.wait_group 0;")

// ---------------- prep: fused tf32 rounding of all sources + pa zero fixup ---
__device__ __forceinline__ void r4cp(float* dst, const float* src, int i) {
    float4 v = *(const float4*)(src + (size_t)i * 4);
    uint4 r;
    r.x = f2tf(v.x); r.y = f2tf(v.y); r.z = f2tf(v.z); r.w = f2tf(v.w);
    *(uint4*)(dst + (size_t)i * 4) = r;
}

__global__ void prep(const float* __restrict__ in_, const float* __restrict__ mem_,
                     const float* __restrict__ pos_, const float* __restrict__ wkv_,
                     const float* __restrict__ wq_, const float* __restrict__ wp_,
                     const float* __restrict__ wo_)
{
    int i = blockIdx.x * 256 + threadIdx.x;
    const int N1 = 1048576, N2 = 524288, N3 = 262144;
    if (i < N1) { r4cp(r_input, in_, i); return; }  i -= N1;
    if (i < N1) { r4cp(r_mem,   mem_, i); return; } i -= N1;
    if (i < N2) { r4cp(r_pos,   pos_, i); return; } i -= N2;
    if (i < N2) { r4cp(r_wkv,   wkv_, i); return; } i -= N2;
    if (i < N3) { r4cp(r_wq,    wq_, i); return; }  i -= N3;
    if (i < N3) { r4cp(r_wp,    wp_, i); return; }  i -= N3;
    if (i < N3) { r4cp(r_wout,  wo_, i); return; }  i -= N3;
    // pa zero-cell fixup: sp=2049 -> j=M-2047 (2047<=M<=4094); sp=4098 -> j=M+2 (M<=2045)
    if (i < H * 4096) {
        int h = i >> 12, M = i & 4095;
        int j = -1;
        if (M >= 2047) { if (M <= 4094) j = M - 2047; }
        else if (M < 2046) j = M + 2;
        if (j >= 0) g_pa[((size_t)h * (BSZ * CS) + M) * T + j] = 0.f;
    }
}

// ---------------- GEMM core (round-13 proven: 128x128, 2-stage cp.async) -----
#define AS_LD 36
#define BS_LD 136
#define STAGE_SZ (128 * AS_LD + 32 * BS_LD)
#define MM_SMEM (2 * STAGE_SZ * 4)   // 71680 B

__device__ __forceinline__ void mma_chunk(float acc[4][4][4],
                                          const uint32_t* __restrict__ As,
                                          const uint32_t* __restrict__ Bs,
                                          int wm, int wn, int lane)
{
    int g = lane >> 2, t = lane & 3;
#pragma unroll
    for (int ks = 0; ks < 4; ks++) {
        uint32_t a[4][4];
#pragma unroll
        for (int mt = 0; mt < 4; mt++) {
            int row = wm * 64 + mt * 16 + g;
            int col = ks * 8 + t;
            a[mt][0] = As[row * AS_LD + col];
            a[mt][1] = As[(row + 8) * AS_LD + col];
            a[mt][2] = As[row * AS_LD + col + 4];
            a[mt][3] = As[(row + 8) * AS_LD + col + 4];
        }
        uint32_t b[4][2];
#pragma unroll
        for (int nt = 0; nt < 4; nt++) {
            int brow = ks * 8 + t;
            int bcol = wn * 32 + nt * 8 + g;
            b[nt][0] = Bs[brow * BS_LD + bcol];
            b[nt][1] = Bs[(brow + 4) * BS_LD + bcol];
        }
#pragma unroll
        for (int mt = 0; mt < 4; mt++)
#pragma unroll
            for (int nt = 0; nt < 4; nt++)
                MMA_TF32(acc[mt][nt], a[mt], b[nt]);
    }
}

__device__ __forceinline__ void store_Cr(float acc[4][4][4], float* C, int ldc,
                                         int m0, int n0, int wm, int wn, int lane, bool rnd)
{
    int g = lane >> 2, t = lane & 3;
#pragma unroll
    for (int mt = 0; mt < 4; mt++) {
#pragma unroll
        for (int nt = 0; nt < 4; nt++) {
            int row = m0 + wm * 64 + mt * 16 + g;
            int col = n0 + wn * 32 + nt * 8 + 2 * t;
            float v0 = acc[mt][nt][0], v1 = acc[mt][nt][1];
            float v2 = acc[mt][nt][2], v3 = acc[mt][nt][3];
            if (rnd) {
                v0 = __uint_as_float(f2tf(v0)); v1 = __uint_as_float(f2tf(v1));
                v2 = __uint_as_float(f2tf(v2)); v3 = __uint_as_float(f2tf(v3));
            }
            *(float2*)(C + (size_t)row * ldc + col) = make_float2(v0, v1);
            *(float2*)(C + (size_t)(row + 8) * ldc + col) = make_float2(v2, v3);
        }
    }
}

// stage: A plain (lda=DIN) or kv-gathered; B row-major ldb
__device__ __forceinline__ void stage_any(uint32_t* As, uint32_t* Bs, int mode,
                                          const float* __restrict__ A,
                                          const float* __restrict__ B, int ldb,
                                          int m0, int n0, int k0, int tid)
{
    if (mode == 0) {
#pragma unroll
        for (int i = 0; i < 4; i++) {
            int s = tid + i * 256;
            int row = s >> 3, kq = (s & 7) * 4;
            int grow = m0 + row;
            int b = grow >> 11, tl = grow & (T - 1);
            const float* Arow = (tl < PS) ? (r_mem + (size_t)(b * PS + tl) * DIN)
                                          : (r_input + (size_t)(b * CS + tl - PS) * DIN);
            cp16(&As[row * AS_LD + kq], Arow + k0 + kq);
        }
    } else {
#pragma unroll
        for (int i = 0; i < 4; i++) {
            int s = tid + i * 256;
            int row = s >> 3, kq = (s & 7) * 4;
            cp16(&As[row * AS_LD + kq], A + (size_t)(m0 + row) * DIN + k0 + kq);
        }
    }
#pragma unroll
    for (int i = 0; i < 4; i++) {
        int s = tid + i * 256;
        int k = s >> 5, n4 = (s & 31) * 4;
        cp16(&Bs[k * BS_LD + n4], B + (size_t)(k0 + k) * ldb + n0 + n4);
    }
}

// fused kv + q + p GEMM: 1408 blocks in one launch (grid-limitation fix)
__global__ __launch_bounds__(256, 2)
void mm_fused3()
{
    extern __shared__ uint32_t dsm[];
    int tid = threadIdx.x, lane = tid & 31, w = tid >> 5;
    int wm = w >> 2, wn = w & 3;

    int bid = blockIdx.x;
    int mode, m0, n0, ldb;
    const float *A = nullptr, *B;
    float* C;
    bool rnd;
    if (bid < 1024) {            // kv: 64 x 16 tiles
        mode = 0; m0 = (bid >> 4) * 128; n0 = (bid & 15) * 128;
        B = r_wkv; ldb = 2 * HD; C = g_kv; rnd = true;
    } else if (bid < 1280) {     // q: 32 x 8 tiles
        int i = bid - 1024;
        mode = 1; m0 = (i >> 3) * 128; n0 = (i & 7) * 128;
        A = r_input; B = r_wq; ldb = HD; C = g_q; rnd = false;
    } else {                     // p: 16 x 8 tiles
        int i = bid - 1280;
        mode = 2; m0 = (i >> 3) * 128; n0 = (i & 7) * 128;
        A = r_pos; B = r_wp; ldb = HD; C = g_p; rnd = false;
    }

    float acc[4][4][4];
#pragma unroll
    for (int i = 0; i < 4; i++)
#pragma unroll
        for (int j = 0; j < 4; j++)
#pragma unroll
            for (int r = 0; r < 4; r++) acc[i][j][r] = 0.f;

    uint32_t* SA[2] = { dsm, dsm + STAGE_SZ };
    uint32_t* SB[2] = { dsm + 128 * AS_LD, dsm + STAGE_SZ + 128 * AS_LD };

    stage_any(SA[0], SB[0], mode, A, B, ldb, m0, n0, 0, tid);  CP_COMMIT;
    stage_any(SA[1], SB[1], mode, A, B, ldb, m0, n0, 32, tid); CP_COMMIT;
    CP_WAIT1;
    __syncthreads();

    const int NK = DIN >> 5;
    for (int k = 0; k < NK; k++) {
        int cur = k & 1;
        mma_chunk(acc, SA[cur], SB[cur], wm, wn, lane);
        __syncthreads();
        if (k + 2 < NK)
            stage_any(SA[cur], SB[cur], mode, A, B, ldb, m0, n0, (k + 2) * 32, tid);
        CP_COMMIT;
        CP_WAIT1;
        __syncthreads();
    }
    store_Cr(acc, C, ldb == 2 * HD ? 2 * HD : HD, m0, n0, wm, wn, lane, rnd);
}

// out GEMM (separate: depends on attention). Round-13 2-stage config.
__global__ __launch_bounds__(256, 2)
void mm_ca(const float* __restrict__ A, const float* __restrict__ B,
           float* __restrict__ C, int M, int N, int K)
{
    extern __shared__ uint32_t dsm[];
    int tid = threadIdx.x, lane = tid & 31, w = tid >> 5;
    int wm = w >> 2, wn = w & 3;
    int m0 = blockIdx.y * 128, n0 = blockIdx.x * 128;

    float acc[4][4][4];
#pragma unroll
    for (int i = 0; i < 4; i++)
#pragma unroll
        for (int j = 0; j < 4; j++)
#pragma unroll
            for (int r = 0; r < 4; r++) acc[i][j][r] = 0.f;

    uint32_t* SA[2] = { dsm, dsm + STAGE_SZ };
    uint32_t* SB[2] = { dsm + 128 * AS_LD, dsm + STAGE_SZ + 128 * AS_LD };

    stage_any(SA[0], SB[0], 1, A, B, N, m0, n0, 0, tid);  CP_COMMIT;
    stage_any(SA[1], SB[1], 1, A, B, N, m0, n0, 32, tid); CP_COMMIT;
    CP_WAIT1;
    __syncthreads();

    int NK = K >> 5;
    for (int k = 0; k < NK; k++) {
        int cur = k & 1;
        mma_chunk(acc, SA[cur], SB[cur], wm, wn, lane);
        __syncthreads();
        if (k + 2 < NK)
            stage_any(SA[cur], SB[cur], 1, A, B, N, m0, n0, (k + 2) * 32, tid);
        CP_COMMIT;
        CP_WAIT1;
        __syncthreads();
    }
    store_Cr(acc, C, N, m0, n0, wm, wn, lane, false);
}

// ---------------- position-attn GEMM with SHIFT-ON-WRITE epilogue ------------
#define PA_LD 68
#define PA_SMEM (2 * 128 * PA_LD * 4)   // 69632 B

__device__ __forceinline__ void scatter_pa(float* __restrict__ Ch, int rp, int cp, float val)
{
    int s = rp + cp;
    int a = (s <= 2046) ? 2 : ((s <= 4094) ? 1 : 0);
    int M = rp - a;
    if (M < 0) return;
    int j = s + 1 - 4096 + (a << 11);
    if (j > (M & (CS - 1)) + PS) return;     // masked cell — overwritten by -1e30 at read
    Ch[(size_t)M * T + j] = val * SCALEF;
}

__global__ __launch_bounds__(256, 2)
void mm_pa2(const float* __restrict__ vvec)
{
    extern __shared__ uint32_t psm[];
    uint32_t* As = psm;                  // 128 x 68 (q+v rows, K-major tf32)
    uint32_t* Bs = psm + 128 * PA_LD;    // 128 x 68 (p rows,   K-major tf32)

    int tid = threadIdx.x, lane = tid & 31, w = tid >> 5;
    int wm = w >> 2, wn = w & 3;
    int h = blockIdx.z;
    int m0 = blockIdx.y * 128, n0 = blockIdx.x * 128;
    int g = lane >> 2, t = lane & 3;

#pragma unroll
    for (int l = 0; l < 8; l++) {
        int idx = tid + l * 256;
        int r = idx >> 4, kq = (idx & 15) * 4;
        float4 a = *(const float4*)(g_q + (size_t)(m0 + r) * HD + h * D + kq);
        float4 vx = *(const float4*)(vvec + h * D + kq);
        uint4 ua;
        ua.x = f2tf(a.x + vx.x); ua.y = f2tf(a.y + vx.y);
        ua.z = f2tf(a.z + vx.z); ua.w = f2tf(a.w + vx.w);
        *(uint4*)&As[r * PA_LD + kq] = ua;
        float4 p4 = *(const float4*)(g_p + (size_t)(n0 + r) * HD + h * D + kq);
        uint4 ub;
        ub.x = f2tf(p4.x); ub.y = f2tf(p4.y); ub.z = f2tf(p4.z); ub.w = f2tf(p4.w);
        *(uint4*)&Bs[r * PA_LD + kq] = ub;
    }
    __syncthreads();

    float acc[4][4][4];
#pragma unroll
    for (int i = 0; i < 4; i++)
#pragma unroll
        for (int j = 0; j < 4; j++)
#pragma unroll
            for (int r = 0; r < 4; r++) acc[i][j][r] = 0.f;

#pragma unroll
    for (int ks = 0; ks < 8; ks++) {
        uint32_t a[4][4];
#pragma unroll
        for (int mt = 0; mt < 4; mt++) {
            int row = wm * 64 + mt * 16 + g;
            int col = ks * 8 + t;
            a[mt][0] = As[row * PA_LD + col];
            a[mt][1] = As[(row + 8) * PA_LD + col];
            a[mt][2] = As[row * PA_LD + col + 4];
            a[mt][3] = As[(row + 8) * PA_LD + col + 4];
        }
        uint32_t b[4][2];
#pragma unroll
        for (int nt = 0; nt < 4; nt++) {
            int bcol = wn * 32 + nt * 8 + g;
            b[nt][0] = Bs[bcol * PA_LD + ks * 8 + t];
            b[nt][1] = Bs[bcol * PA_LD + ks * 8 + t + 4];
        }
#pragma unroll
        for (int mt = 0; mt < 4; mt++)
#pragma unroll
            for (int nt = 0; nt < 4; nt++)
                MMA_TF32(acc[mt][nt], a[mt], b[nt]);
    }

    float* Ch = g_pa + (size_t)h * (BSZ * CS) * T;
#pragma unroll
    for (int mt = 0; mt < 4; mt++) {
#pragma unroll
        for (int nt = 0; nt < 4; nt++) {
            int row0 = m0 + wm * 64 + mt * 16 + g;
            int col0 = n0 + wn * 32 + nt * 8 + 2 * t;
            scatter_pa(Ch, row0,     col0,     acc[mt][nt][0]);
            scatter_pa(Ch, row0,     col0 + 1, acc[mt][nt][1]);
            scatter_pa(Ch, row0 + 8, col0,     acc[mt][nt][2]);
            scatter_pa(Ch, row0 + 8, col0 + 1, acc[mt][nt][3]);
        }
    }
}

// ---------------- flash attention (round-13 form: no hoist) -------------------
#define AT_LD 68
#define ATT_SMEM ((2 * 2 * 64 * AT_LD + 128 * AT_LD) * 4)   // 104448 B

__device__ __forceinline__ void stage_kv_tile(uint32_t* buf, int b, int h, int j0, int tid)
{
#pragma unroll
    for (int l = 0; l < 4; l++) {
        int idx = tid + l * 256;
        int r = idx >> 4, q = idx & 15;
        const float* src = g_kv + (size_t)(b * T + j0 + r) * (2 * HD) + h * D + q * 4;
        cp16(buf + r * AT_LD + q * 4, src);                   // K
        cp16(buf + 64 * AT_LD + r * AT_LD + q * 4, src + HD); // V
    }
}

__global__ __launch_bounds__(256, 2)
void attn_tc(const float* __restrict__ u)
{
    extern __shared__ uint32_t sm[];
    uint32_t* Ps = sm + 2 * 2 * 64 * AT_LD;   // 128 x 68 (Q staging, then P)

    int tid = threadIdx.x, lane = tid & 31, w = tid >> 5;
    int b = blockIdx.z, h = blockIdx.y;
    int q0 = (int)(gridDim.x - 1 - blockIdx.x) * 128;
    int g = lane >> 2, t = lane & 3;

    // Q(+u), pre-scaled by SCALEF (exact power of 2), tf32
    for (int i = tid; i < 128 * 16; i += 256) {
        int r = i >> 4, d4 = (i & 15) * 4;
        float4 qv = *(const float4*)(g_q + (size_t)(b * CS + q0 + r) * HD + h * D + d4);
        float4 uv = *(const float4*)(u + h * D + d4);
        Ps[r * AT_LD + d4 + 0] = f2tf((qv.x + uv.x) * SCALEF);
        Ps[r * AT_LD + d4 + 1] = f2tf((qv.y + uv.y) * SCALEF);
        Ps[r * AT_LD + d4 + 2] = f2tf((qv.z + uv.z) * SCALEF);
        Ps[r * AT_LD + d4 + 3] = f2tf((qv.w + uv.w) * SCALEF);
    }
    __syncthreads();

    uint32_t qf[8][4];
    {
        int r0 = w * 16 + g;
#pragma unroll
        for (int ks = 0; ks < 8; ks++) {
            qf[ks][0] = Ps[r0 * AT_LD + ks * 8 + t];
            qf[ks][1] = Ps[(r0 + 8) * AT_LD + ks * 8 + t];
            qf[ks][2] = Ps[r0 * AT_LD + ks * 8 + t + 4];
            qf[ks][3] = Ps[(r0 + 8) * AT_LD + ks * 8 + t + 4];
        }
    }

    float of[8][4];
#pragma unroll
    for (int nt = 0; nt < 8; nt++)
#pragma unroll
        for (int r = 0; r < 4; r++) of[nt][r] = 0.f;
    float m0r = -1e30f, m1r = -1e30f, l0 = 0.f, l1 = 0.f;

    int iq_g = q0 + w * 16 + g;
    int Mrow_g = b * CS + iq_g;
    int pr0 = (w * 16 + g) * AT_LD, pr8 = (w * 16 + g + 8) * AT_LD;
    int ntiles = q0 / 64 + 18;

    const float* pab0 = g_pa + ((size_t)h * (BSZ * CS) + Mrow_g) * T;
    const float* pab8 = pab0 + (size_t)8 * T;

    stage_kv_tile(sm, b, h, 0, tid);   // tile 0 -> buf 0
    CP_COMMIT;

    for (int tt = 0; tt < ntiles; tt++) {
        int cur = tt & 1;
        uint32_t* Kc = sm + cur * (2 * 64 * AT_LD);
        uint32_t* Vc = Kc + 64 * AT_LD;
        int j0 = tt * 64;

        __syncthreads();   // all warps done reading buf[1-cur] (iter tt-1)
        if (tt + 1 < ntiles) {
            stage_kv_tile(sm + (1 - cur) * (2 * 64 * AT_LD), b, h, j0 + 64, tid);
            CP_COMMIT;
            CP_WAIT1;      // tile tt arrived (tt+1 in flight)
        } else {
            CP_WAIT0;
        }
        __syncthreads();

        // S = (Q+u)*SCALE @ K^T
        float sf[8][4];
#pragma unroll
        for (int nt = 0; nt < 8; nt++) {
            sf[nt][0] = sf[nt][1] = sf[nt][2] = sf[nt][3] = 0.f;
#pragma unroll
            for (int ks = 0; ks < 8; ks++) {
                uint32_t bb[2];
                bb[0] = Kc[(nt * 8 + g) * AT_LD + ks * 8 + t];
                bb[1] = Kc[(nt * 8 + g) * AT_LD + ks * 8 + t + 4];
                MMA_TF32(sf[nt], qf[ks], bb);
            }
        }

        // add pre-shifted pre-scaled pos (contiguous float2 loads) + mask
        bool need_mask = (tt >= ntiles - 2);
#pragma unroll
        for (int nt = 0; nt < 8; nt++) {
            int j = j0 + nt * 8 + 2 * t;
            float2 p0 = __ldg((const float2*)(pab0 + j));
            float2 p8 = __ldg((const float2*)(pab8 + j));
            sf[nt][0] += p0.x; sf[nt][1] += p0.y;
            sf[nt][2] += p8.x; sf[nt][3] += p8.y;
            if (need_mask) {
                int lim0 = iq_g + PS, lim1 = lim0 + 8;
                if (j     > lim0) sf[nt][0] = -1e30f;
                if (j + 1 > lim0) sf[nt][1] = -1e30f;
                if (j     > lim1) sf[nt][2] = -1e30f;
                if (j + 1 > lim1) sf[nt][3] = -1e30f;
            }
        }

        // online softmax
        float tm0 = -1e30f, tm1 = -1e30f;
#pragma unroll
        for (int nt = 0; nt < 8; nt++) {
            tm0 = fmaxf(tm0, fmaxf(sf[nt][0], sf[nt][1]));
            tm1 = fmaxf(tm1, fmaxf(sf[nt][2], sf[nt][3]));
        }
        tm0 = fmaxf(tm0, __shfl_xor_sync(0xffffffffu, tm0, 1));
        tm0 = fmaxf(tm0, __shfl_xor_sync(0xffffffffu, tm0, 2));
        tm1 = fmaxf(tm1, __shfl_xor_sync(0xffffffffu, tm1, 1));
        tm1 = fmaxf(tm1, __shfl_xor_sync(0xffffffffu, tm1, 2));
        float nm0 = fmaxf(m0r, tm0), nm1 = fmaxf(m1r, tm1);
        float cr0 = __expf(m0r - nm0), cr1 = __expf(m1r - nm1);

        float ps0 = 0.f, ps1 = 0.f;
#pragma unroll
        for (int nt = 0; nt < 8; nt++) {
            float e0 = __expf(sf[nt][0] - nm0);
            float e1 = __expf(sf[nt][1] - nm0);
            float e2 = __expf(sf[nt][2] - nm1);
            float e3 = __expf(sf[nt][3] - nm1);
            int col = nt * 8 + 2 * t;
            Ps[pr0 + col]     = f2tf(e0);
            Ps[pr0 + col + 1] = f2tf(e1);
            Ps[pr8 + col]     = f2tf(e2);
            Ps[pr8 + col + 1] = f2tf(e3);
            ps0 += e0 + e1;
            ps1 += e2 + e3;
        }
        ps0 += __shfl_xor_sync(0xffffffffu, ps0, 1);
        ps0 += __shfl_xor_sync(0xffffffffu, ps0, 2);
        ps1 += __shfl_xor_sync(0xffffffffu, ps1, 1);
        ps1 += __shfl_xor_sync(0xffffffffu, ps1, 2);
        l0 = l0 * cr0 + ps0;
        l1 = l1 * cr1 + ps1;
        m0r = nm0; m1r = nm1;
#pragma unroll
        for (int nt = 0; nt < 8; nt++) {
            of[nt][0] *= cr0; of[nt][1] *= cr0;
            of[nt][2] *= cr1; of[nt][3] *= cr1;
        }
        __syncwarp();

        uint32_t af[8][4];
#pragma unroll
        for (int ks = 0; ks < 8; ks++) {
            af[ks][0] = Ps[pr0 + ks * 8 + t];
            af[ks][1] = Ps[pr8 + ks * 8 + t];
            af[ks][2] = Ps[pr0 + ks * 8 + t + 4];
            af[ks][3] = Ps[pr8 + ks * 8 + t + 4];
        }
#pragma unroll
        for (int nt = 0; nt < 8; nt++) {
#pragma unroll
            for (int ks = 0; ks < 8; ks++) {
                uint32_t bb[2];
                bb[0] = Vc[(ks * 8 + t) * AT_LD + nt * 8 + g];
                bb[1] = Vc[(ks * 8 + t + 4) * AT_LD + nt * 8 + g];
                MMA_TF32(of[nt], af[ks], bb);
            }
        }
        __syncwarp();
    }

    float i0 = 1.f / l0, i1 = 1.f / l1;
    int orow = b * CS + q0 + w * 16 + g;
#pragma unroll
    for (int nt = 0; nt < 8; nt++) {
        int col = h * D + nt * 8 + 2 * t;
        float2 v0 = make_float2(__uint_as_float(f2tf(of[nt][0] * i0)),
                                __uint_as_float(f2tf(of[nt][1] * i0)));
        float2 v1 = make_float2(__uint_as_float(f2tf(of[nt][2] * i1)),
                                __uint_as_float(f2tf(of[nt][3] * i1)));
        *(float2*)(g_awv + (size_t)orow * HD + col) = v0;
        *(float2*)(g_awv + (size_t)(orow + 8) * HD + col) = v1;
    }
}

// ---------------- launch -------------------------------------------------------
extern "C" void kernel_launch(void* const* d_in, const int* in_sizes, int n_in,
                              void* d_out, int out_size)
{
    const float* input  = (const float*)d_in[0];
    const float* pos    = (const float*)d_in[1];
    const float* memory = (const float*)d_in[2];
    const float* u      = (const float*)d_in[3];
    const float* v      = (const float*)d_in[4];
    const float* Wkv    = (const float*)d_in[5];
    const float* Wq     = (const float*)d_in[6];
    const float* Wp     = (const float*)d_in[7];
    const float* Wout   = (const float*)d_in[8];
    float* out = (float*)d_out;

    float *pawv, *prwo;
    cudaGetSymbolAddress((void**)&pawv, g_awv);
    cudaGetSymbolAddress((void**)&prwo, r_wout);

    cudaFuncSetAttribute(mm_fused3, cudaFuncAttributeMaxDynamicSharedMemorySize, MM_SMEM);
    cudaFuncSetAttribute(mm_ca,     cudaFuncAttributeMaxDynamicSharedMemorySize, MM_SMEM);
    cudaFuncSetAttribute(mm_pa2,    cudaFuncAttributeMaxDynamicSharedMemorySize, PA_SMEM);
    cudaFuncSetAttribute(attn_tc,   cudaFuncAttributeMaxDynamicSharedMemorySize, ATT_SMEM);

    // launch 0: fused tf32 pre-round of all sources + pa zero-cell fixup
    prep<<<15616, 256>>>(input, memory, pos, Wkv, Wq, Wp, Wout);
    // launch 1: fused kv + q + p GEMMs (1408 blocks, one wave-packed launch)
    mm_fused3<<<1408, 256, MM_SMEM>>>();
    // launch 2: pos-attn per head, shift-on-write  (16 x 4096 x 2048 x 64)
    mm_pa2<<<dim3(16, 32, H), 256, PA_SMEM>>>(v);
    // launch 3: flash attention
    attn_tc<<<dim3(8, H, BSZ), 256, ATT_SMEM>>>(u);
    // launch 4: out = awv @ W_out             (4096 x 1024 x 1024)
    mm_ca<<<dim3(8, 32), 256, MM_SMEM>>>(pawv, prwo, out, BSZ * CS, DIN, HD);
}

// round 16
// speedup vs baseline: 1.2671x; 1.2026x over previous
#include <cuda_runtime.h>
#include <cuda_fp16.h>
#include <cstdint>

#define BSZ 4
#define CS  1024
#define PS  1024
#define DIN 1024
#define H   16
#define D   64
#define T   2048
#define HD  (H * D)
#define SCALEF 0.125f

// ---------------- scratch (static device globals; allocation-free) ----------
__device__ __half g_k16[(size_t)BSZ * T * HD];      // [b*T+t][dim] fp16 keys
__device__ __half g_vT [(size_t)BSZ * HD * T];      // [b][dim][t]  fp16 values (transposed)
__device__ float g_q  [(size_t)BSZ * CS * HD];
__device__ float g_p  [(size_t)T * HD];
__device__ float g_pa [(size_t)H * BSZ * CS * T];   // [h][M][j] SHIFTED+SCALED position scores
__device__ float g_awv[(size_t)BSZ * CS * HD];      // tf32-rounded attention output

// tf32-rounded copies of GEMM sources
__device__ float r_input[(size_t)BSZ * CS * DIN];
__device__ float r_mem  [(size_t)BSZ * PS * DIN];
__device__ float r_pos  [(size_t)T * DIN];
__device__ float r_wkv  [(size_t)DIN * 2 * HD];
__device__ float r_wq   [(size_t)DIN * HD];
__device__ float r_wp   [(size_t)DIN * HD];
__device__ float r_wout [(size_t)HD * DIN];

// ---------------- helpers ----------------------------------------------------
__device__ __forceinline__ uint32_t f2tf(float x) {
    uint32_t u;
    asm("cvt.rna.tf32.f32 %0, %1;" : "=r"(u) : "f"(x));
    return u;
}
__device__ __forceinline__ uint32_t f22h2(float lo, float hi) {
    __half2 h = __floats2half2_rn(lo, hi);
    return *(uint32_t*)&h;
}

#define MMA_TF32(c, a, b) \
    asm volatile("mma.sync.aligned.m16n8k8.row.col.f32.tf32.tf32.f32 " \
                 "{%0,%1,%2,%3},{%4,%5,%6,%7},{%8,%9},{%0,%1,%2,%3};" \
                 : "+f"(c[0]), "+f"(c[1]), "+f"(c[2]), "+f"(c[3]) \
                 : "r"(a[0]), "r"(a[1]), "r"(a[2]), "r"(a[3]), "r"(b[0]), "r"(b[1]))

#define MMA_F16(c, a, b) \
    asm volatile("mma.sync.aligned.m16n8k16.row.col.f32.f16.f16.f32 " \
                 "{%0,%1,%2,%3},{%4,%5,%6,%7},{%8,%9},{%0,%1,%2,%3};" \
                 : "+f"(c[0]), "+f"(c[1]), "+f"(c[2]), "+f"(c[3]) \
                 : "r"(a[0]), "r"(a[1]), "r"(a[2]), "r"(a[3]), "r"(b[0]), "r"(b[1]))

__device__ __forceinline__ void cp16(uint32_t* smem_dst, const void* gmem_src) {
    uint32_t sa = (uint32_t)__cvta_generic_to_shared(smem_dst);
    asm volatile("cp.async.cg.shared.global [%0], [%1], 16;" :: "r"(sa), "l"(gmem_src));
}
#define CP_COMMIT asm volatile("cp.async.commit_group;")
#define CP_WAIT1  asm volatile("cp.async.wait_group 1;")
#define CP_WAIT0  asm volatile("cp.async.wait_group 0;")

// ---------------- prep: fused tf32 rounding of all sources + pa zero fixup ---
__device__ __forceinline__ void r4cp(float* dst, const float* src, int i) {
    float4 v = *(const float4*)(src + (size_t)i * 4);
    uint4 r;
    r.x = f2tf(v.x); r.y = f2tf(v.y); r.z = f2tf(v.z); r.w = f2tf(v.w);
    *(uint4*)(dst + (size_t)i * 4) = r;
}

__global__ void prep(const float* __restrict__ in_, const float* __restrict__ mem_,
                     const float* __restrict__ pos_, const float* __restrict__ wkv_,
                     const float* __restrict__ wq_, const float* __restrict__ wp_,
                     const float* __restrict__ wo_)
{
    int i = blockIdx.x * 256 + threadIdx.x;
    const int N1 = 1048576, N2 = 524288, N3 = 262144;
    if (i < N1) { r4cp(r_input, in_, i); return; }  i -= N1;
    if (i < N1) { r4cp(r_mem,   mem_, i); return; } i -= N1;
    if (i < N2) { r4cp(r_pos,   pos_, i); return; } i -= N2;
    if (i < N2) { r4cp(r_wkv,   wkv_, i); return; } i -= N2;
    if (i < N3) { r4cp(r_wq,    wq_, i); return; }  i -= N3;
    if (i < N3) { r4cp(r_wp,    wp_, i); return; }  i -= N3;
    if (i < N3) { r4cp(r_wout,  wo_, i); return; }  i -= N3;
    // pa zero-cell fixup: sp=2049 -> j=M-2047 (2047<=M<=4094); sp=4098 -> j=M+2 (M<=2045)
    if (i < H * 4096) {
        int h = i >> 12, M = i & 4095;
        int j = -1;
        if (M >= 2047) { if (M <= 4094) j = M - 2047; }
        else if (M < 2046) j = M + 2;
        if (j >= 0) g_pa[((size_t)h * (BSZ * CS) + M) * T + j] = 0.f;
    }
}

// ---------------- GEMM core (128x128, 2-stage cp.async) ----------------------
#define AS_LD 36
#define BS_LD 136
#define STAGE_SZ (128 * AS_LD + 32 * BS_LD)
#define MM_SMEM (2 * STAGE_SZ * 4)   // 71680 B

__device__ __forceinline__ void mma_chunk(float acc[4][4][4],
                                          const uint32_t* __restrict__ As,
                                          const uint32_t* __restrict__ Bs,
                                          int wm, int wn, int lane)
{
    int g = lane >> 2, t = lane & 3;
#pragma unroll
    for (int ks = 0; ks < 4; ks++) {
        uint32_t a[4][4];
#pragma unroll
        for (int mt = 0; mt < 4; mt++) {
            int row = wm * 64 + mt * 16 + g;
            int col = ks * 8 + t;
            a[mt][0] = As[row * AS_LD + col];
            a[mt][1] = As[(row + 8) * AS_LD + col];
            a[mt][2] = As[row * AS_LD + col + 4];
            a[mt][3] = As[(row + 8) * AS_LD + col + 4];
        }
        uint32_t b[4][2];
#pragma unroll
        for (int nt = 0; nt < 4; nt++) {
            int brow = ks * 8 + t;
            int bcol = wn * 32 + nt * 8 + g;
            b[nt][0] = Bs[brow * BS_LD + bcol];
            b[nt][1] = Bs[(brow + 4) * BS_LD + bcol];
        }
#pragma unroll
        for (int mt = 0; mt < 4; mt++)
#pragma unroll
            for (int nt = 0; nt < 4; nt++)
                MMA_TF32(acc[mt][nt], a[mt], b[nt]);
    }
}

__device__ __forceinline__ void store_Cr(float acc[4][4][4], float* C, int ldc,
                                         int m0, int n0, int wm, int wn, int lane)
{
    int g = lane >> 2, t = lane & 3;
#pragma unroll
    for (int mt = 0; mt < 4; mt++) {
#pragma unroll
        for (int nt = 0; nt < 4; nt++) {
            int row = m0 + wm * 64 + mt * 16 + g;
            int col = n0 + wn * 32 + nt * 8 + 2 * t;
            *(float2*)(C + (size_t)row * ldc + col) =
                make_float2(acc[mt][nt][0], acc[mt][nt][1]);
            *(float2*)(C + (size_t)(row + 8) * ldc + col) =
                make_float2(acc[mt][nt][2], acc[mt][nt][3]);
        }
    }
}

// kv epilogue: K half rows to g_k16, V half transposed to g_vT
__device__ __forceinline__ void store_kv_half(float acc[4][4][4], int m0, int n0,
                                              int wm, int wn, int lane)
{
    int g = lane >> 2, t = lane & 3;
#pragma unroll
    for (int mt = 0; mt < 4; mt++) {
#pragma unroll
        for (int nt = 0; nt < 4; nt++) {
            int row = m0 + wm * 64 + mt * 16 + g;
            int col = n0 + wn * 32 + nt * 8 + 2 * t;
            float v0 = acc[mt][nt][0], v1 = acc[mt][nt][1];
            float v2 = acc[mt][nt][2], v3 = acc[mt][nt][3];
            if (col < 1024) {
                *(uint32_t*)(g_k16 + (size_t)row * HD + col)       = f22h2(v0, v1);
                *(uint32_t*)(g_k16 + (size_t)(row + 8) * HD + col) = f22h2(v2, v3);
            } else {
                int d = col - 1024;
                int bb = row >> 11, tr = row & (T - 1);
                __half* vb = g_vT + (size_t)bb * HD * T;
                vb[(size_t)d * T + tr]           = __float2half_rn(v0);
                vb[(size_t)(d + 1) * T + tr]     = __float2half_rn(v1);
                vb[(size_t)d * T + tr + 8]       = __float2half_rn(v2);
                vb[(size_t)(d + 1) * T + tr + 8] = __float2half_rn(v3);
            }
        }
    }
}

// stage: A plain (lda=DIN) or kv-gathered; B row-major ldb
__device__ __forceinline__ void stage_any(uint32_t* As, uint32_t* Bs, int mode,
                                          const float* __restrict__ A,
                                          const float* __restrict__ B, int ldb,
                                          int m0, int n0, int k0, int tid)
{
    if (mode == 0) {
#pragma unroll
        for (int i = 0; i < 4; i++) {
            int s = tid + i * 256;
            int row = s >> 3, kq = (s & 7) * 4;
            int grow = m0 + row;
            int b = grow >> 11, tl = grow & (T - 1);
            const float* Arow = (tl < PS) ? (r_mem + (size_t)(b * PS + tl) * DIN)
                                          : (r_input + (size_t)(b * CS + tl - PS) * DIN);
            cp16(&As[row * AS_LD + kq], Arow + k0 + kq);
        }
    } else {
#pragma unroll
        for (int i = 0; i < 4; i++) {
            int s = tid + i * 256;
            int row = s >> 3, kq = (s & 7) * 4;
            cp16(&As[row * AS_LD + kq], A + (size_t)(m0 + row) * DIN + k0 + kq);
        }
    }
#pragma unroll
    for (int i = 0; i < 4; i++) {
        int s = tid + i * 256;
        int k = s >> 5, n4 = (s & 31) * 4;
        cp16(&Bs[k * BS_LD + n4], B + (size_t)(k0 + k) * ldb + n0 + n4);
    }
}

// fused kv + q + p GEMM: 1408 blocks in one launch
__global__ __launch_bounds__(256, 2)
void mm_fused3()
{
    extern __shared__ uint32_t dsm[];
    int tid = threadIdx.x, lane = tid & 31, w = tid >> 5;
    int wm = w >> 2, wn = w & 3;

    int bid = blockIdx.x;
    int mode, m0, n0, ldb;
    const float *A = nullptr, *B;
    float* C = nullptr;
    if (bid < 1024) {            // kv: 64 x 16 tiles
        mode = 0; m0 = (bid >> 4) * 128; n0 = (bid & 15) * 128;
        B = r_wkv; ldb = 2 * HD;
    } else if (bid < 1280) {     // q: 32 x 8 tiles
        int i = bid - 1024;
        mode = 1; m0 = (i >> 3) * 128; n0 = (i & 7) * 128;
        A = r_input; B = r_wq; ldb = HD; C = g_q;
    } else {                     // p: 16 x 8 tiles
        int i = bid - 1280;
        mode = 2; m0 = (i >> 3) * 128; n0 = (i & 7) * 128;
        A = r_pos; B = r_wp; ldb = HD; C = g_p;
    }

    float acc[4][4][4];
#pragma unroll
    for (int i = 0; i < 4; i++)
#pragma unroll
        for (int j = 0; j < 4; j++)
#pragma unroll
            for (int r = 0; r < 4; r++) acc[i][j][r] = 0.f;

    uint32_t* SA[2] = { dsm, dsm + STAGE_SZ };
    uint32_t* SB[2] = { dsm + 128 * AS_LD, dsm + STAGE_SZ + 128 * AS_LD };

    stage_any(SA[0], SB[0], mode, A, B, ldb, m0, n0, 0, tid);  CP_COMMIT;
    stage_any(SA[1], SB[1], mode, A, B, ldb, m0, n0, 32, tid); CP_COMMIT;
    CP_WAIT1;
    __syncthreads();

    const int NK = DIN >> 5;
    for (int k = 0; k < NK; k++) {
        int cur = k & 1;
        mma_chunk(acc, SA[cur], SB[cur], wm, wn, lane);
        __syncthreads();
        if (k + 2 < NK)
            stage_any(SA[cur], SB[cur], mode, A, B, ldb, m0, n0, (k + 2) * 32, tid);
        CP_COMMIT;
        CP_WAIT1;
        __syncthreads();
    }
    if (mode == 0) store_kv_half(acc, m0, n0, wm, wn, lane);
    else           store_Cr(acc, C, HD, m0, n0, wm, wn, lane);
}

// out GEMM (depends on attention)
__global__ __launch_bounds__(256, 2)
void mm_ca(const float* __restrict__ A, const float* __restrict__ B,
           float* __restrict__ C, int M, int N, int K)
{
    extern __shared__ uint32_t dsm[];
    int tid = threadIdx.x, lane = tid & 31, w = tid >> 5;
    int wm = w >> 2, wn = w & 3;
    int m0 = blockIdx.y * 128, n0 = blockIdx.x * 128;

    float acc[4][4][4];
#pragma unroll
    for (int i = 0; i < 4; i++)
#pragma unroll
        for (int j = 0; j < 4; j++)
#pragma unroll
            for (int r = 0; r < 4; r++) acc[i][j][r] = 0.f;

    uint32_t* SA[2] = { dsm, dsm + STAGE_SZ };
    uint32_t* SB[2] = { dsm + 128 * AS_LD, dsm + STAGE_SZ + 128 * AS_LD };

    stage_any(SA[0], SB[0], 1, A, B, N, m0, n0, 0, tid);  CP_COMMIT;
    stage_any(SA[1], SB[1], 1, A, B, N, m0, n0, 32, tid); CP_COMMIT;
    CP_WAIT1;
    __syncthreads();

    int NK = K >> 5;
    for (int k = 0; k < NK; k++) {
        int cur = k & 1;
        mma_chunk(acc, SA[cur], SB[cur], wm, wn, lane);
        __syncthreads();
        if (k + 2 < NK)
            stage_any(SA[cur], SB[cur], 1, A, B, N, m0, n0, (k + 2) * 32, tid);
        CP_COMMIT;
        CP_WAIT1;
        __syncthreads();
    }
    store_Cr(acc, C, N, m0, n0, wm, wn, lane);
}

// ---------------- position-attn GEMM with SHIFT-ON-WRITE epilogue ------------
#define PA_LD 68
#define PA_SMEM (2 * 128 * PA_LD * 4)   // 69632 B

__device__ __forceinline__ void scatter_pa(float* __restrict__ Ch, int rp, int cp, float val)
{
    int s = rp + cp;
    int a = (s <= 2046) ? 2 : ((s <= 4094) ? 1 : 0);
    int M = rp - a;
    if (M < 0) return;
    int j = s + 1 - 4096 + (a << 11);
    if (j > (M & (CS - 1)) + PS) return;     // masked cell — overwritten by -1e30 at read
    Ch[(size_t)M * T + j] = val * SCALEF;
}

__global__ __launch_bounds__(256, 2)
void mm_pa2(const float* __restrict__ vvec)
{
    extern __shared__ uint32_t psm[];
    uint32_t* As = psm;
    uint32_t* Bs = psm + 128 * PA_LD;

    int tid = threadIdx.x, lane = tid & 31, w = tid >> 5;
    int wm = w >> 2, wn = w & 3;
    int h = blockIdx.z;
    int m0 = blockIdx.y * 128, n0 = blockIdx.x * 128;
    int g = lane >> 2, t = lane & 3;

#pragma unroll
    for (int l = 0; l < 8; l++) {
        int idx = tid + l * 256;
        int r = idx >> 4, kq = (idx & 15) * 4;
        float4 a = *(const float4*)(g_q + (size_t)(m0 + r) * HD + h * D + kq);
        float4 vx = *(const float4*)(vvec + h * D + kq);
        uint4 ua;
        ua.x = f2tf(a.x + vx.x); ua.y = f2tf(a.y + vx.y);
        ua.z = f2tf(a.z + vx.z); ua.w = f2tf(a.w + vx.w);
        *(uint4*)&As[r * PA_LD + kq] = ua;
        float4 p4 = *(const float4*)(g_p + (size_t)(n0 + r) * HD + h * D + kq);
        uint4 ub;
        ub.x = f2tf(p4.x); ub.y = f2tf(p4.y); ub.z = f2tf(p4.z); ub.w = f2tf(p4.w);
        *(uint4*)&Bs[r * PA_LD + kq] = ub;
    }
    __syncthreads();

    float acc[4][4][4];
#pragma unroll
    for (int i = 0; i < 4; i++)
#pragma unroll
        for (int j = 0; j < 4; j++)
#pragma unroll
            for (int r = 0; r < 4; r++) acc[i][j][r] = 0.f;

#pragma unroll
    for (int ks = 0; ks < 8; ks++) {
        uint32_t a[4][4];
#pragma unroll
        for (int mt = 0; mt < 4; mt++) {
            int row = wm * 64 + mt * 16 + g;
            int col = ks * 8 + t;
            a[mt][0] = As[row * PA_LD + col];
            a[mt][1] = As[(row + 8) * PA_LD + col];
            a[mt][2] = As[row * PA_LD + col + 4];
            a[mt][3] = As[(row + 8) * PA_LD + col + 4];
        }
        uint32_t b[4][2];
#pragma unroll
        for (int nt = 0; nt < 4; nt++) {
            int bcol = wn * 32 + nt * 8 + g;
            b[nt][0] = Bs[bcol * PA_LD + ks * 8 + t];
            b[nt][1] = Bs[bcol * PA_LD + ks * 8 + t + 4];
        }
#pragma unroll
        for (int mt = 0; mt < 4; mt++)
#pragma unroll
            for (int nt = 0; nt < 4; nt++)
                MMA_TF32(acc[mt][nt], a[mt], b[nt]);
    }

    float* Ch = g_pa + (size_t)h * (BSZ * CS) * T;
#pragma unroll
    for (int mt = 0; mt < 4; mt++) {
#pragma unroll
        for (int nt = 0; nt < 4; nt++) {
            int row0 = m0 + wm * 64 + mt * 16 + g;
            int col0 = n0 + wn * 32 + nt * 8 + 2 * t;
            scatter_pa(Ch, row0,     col0,     acc[mt][nt][0]);
            scatter_pa(Ch, row0,     col0 + 1, acc[mt][nt][1]);
            scatter_pa(Ch, row0 + 8, col0,     acc[mt][nt][2]);
            scatter_pa(Ch, row0 + 8, col0 + 1, acc[mt][nt][3]);
        }
    }
}

// ---------------- flash attention: fp16 m16n8k16 pipeline ---------------------
#define KT_LD 36                                     // 32 half2 + 4 pad per row
#define ATT_SMEM ((4 * 64 * KT_LD + 128 * KT_LD) * 4)   // 55296 B

__device__ __forceinline__ void stage_kv16(uint32_t* kbuf, uint32_t* vbuf,
                                           int b, int h, int j0, int tid)
{
#pragma unroll
    for (int l = 0; l < 2; l++) {
        int idx = tid + l * 256;
        int r = idx >> 3, q = idx & 7;
        cp16(kbuf + r * KT_LD + q * 4,
             g_k16 + (size_t)(b * T + j0 + r) * HD + h * D + q * 8);
    }
#pragma unroll
    for (int l = 0; l < 2; l++) {
        int idx = tid + l * 256;
        int r = idx >> 3, q = idx & 7;
        cp16(vbuf + r * KT_LD + q * 4,
             g_vT + ((size_t)b * HD + h * D + r) * T + j0 + q * 8);
    }
}

__global__ __launch_bounds__(256, 2)
void attn_tc(const float* __restrict__ u)
{
    extern __shared__ uint32_t sm[];
    uint32_t* Ps = sm + 4 * 64 * KT_LD;   // 128 x KT_LD (Q staging as half2, then P)

    int tid = threadIdx.x, lane = tid & 31, w = tid >> 5;
    int b = blockIdx.z, h = blockIdx.y;
    int q0 = (int)(gridDim.x - 1 - blockIdx.x) * 128;
    int g = lane >> 2, t = lane & 3;

    // Q(+u)*SCALE as half2
    for (int i = tid; i < 128 * 16; i += 256) {
        int r = i >> 4, c = i & 15;
        float4 qv = *(const float4*)(g_q + (size_t)(b * CS + q0 + r) * HD + h * D + c * 4);
        float4 uv = *(const float4*)(u + h * D + c * 4);
        Ps[r * KT_LD + c * 2]     = f22h2((qv.x + uv.x) * SCALEF, (qv.y + uv.y) * SCALEF);
        Ps[r * KT_LD + c * 2 + 1] = f22h2((qv.z + uv.z) * SCALEF, (qv.w + uv.w) * SCALEF);
    }
    __syncthreads();

    uint32_t qf[4][4];
    {
        int r0 = w * 16 + g;
#pragma unroll
        for (int ks2 = 0; ks2 < 4; ks2++) {
            qf[ks2][0] = Ps[r0 * KT_LD + ks2 * 8 + t];
            qf[ks2][1] = Ps[(r0 + 8) * KT_LD + ks2 * 8 + t];
            qf[ks2][2] = Ps[r0 * KT_LD + ks2 * 8 + t + 4];
            qf[ks2][3] = Ps[(r0 + 8) * KT_LD + ks2 * 8 + t + 4];
        }
    }

    float of[8][4];
#pragma unroll
    for (int nt = 0; nt < 8; nt++)
#pragma unroll
        for (int r = 0; r < 4; r++) of[nt][r] = 0.f;
    float m0r = -1e30f, m1r = -1e30f, l0 = 0.f, l1 = 0.f;

    int iq_g = q0 + w * 16 + g;
    int Mrow_g = b * CS + iq_g;
    int pr0 = (w * 16 + g) * KT_LD, pr8 = pr0 + 8 * KT_LD;
    int ntiles = q0 / 64 + 18;

    const float* pab0 = g_pa + ((size_t)h * (BSZ * CS) + Mrow_g) * T;
    const float* pab8 = pab0 + (size_t)8 * T;

    stage_kv16(sm, sm + 2 * 64 * KT_LD, b, h, 0, tid);
    CP_COMMIT;

    for (int tt = 0; tt < ntiles; tt++) {
        int cur = tt & 1;
        uint32_t* Kc = sm + cur * (64 * KT_LD);
        uint32_t* Vc = sm + 2 * 64 * KT_LD + cur * (64 * KT_LD);
        int j0 = tt * 64;

        __syncthreads();
        if (tt + 1 < ntiles) {
            stage_kv16(sm + (1 - cur) * (64 * KT_LD),
                       sm + 2 * 64 * KT_LD + (1 - cur) * (64 * KT_LD), b, h, j0 + 64, tid);
            CP_COMMIT;
            CP_WAIT1;
        } else {
            CP_WAIT0;
        }
        __syncthreads();

        // S = (Q+u)*SCALE @ K^T  (fp16 m16n8k16)
        float sf[8][4];
#pragma unroll
        for (int nt = 0; nt < 8; nt++) {
            sf[nt][0] = sf[nt][1] = sf[nt][2] = sf[nt][3] = 0.f;
#pragma unroll
            for (int ks2 = 0; ks2 < 4; ks2++) {
                uint32_t bb[2];
                bb[0] = Kc[(nt * 8 + g) * KT_LD + ks2 * 8 + t];
                bb[1] = Kc[(nt * 8 + g) * KT_LD + ks2 * 8 + t + 4];
                MMA_F16(sf[nt], qf[ks2], bb);
            }
        }

        // add pre-shifted pre-scaled pos + mask
        bool need_mask = (tt >= ntiles - 2);
#pragma unroll
        for (int nt = 0; nt < 8; nt++) {
            int j = j0 + nt * 8 + 2 * t;
            float2 p0 = __ldg((const float2*)(pab0 + j));
            float2 p8 = __ldg((const float2*)(pab8 + j));
            sf[nt][0] += p0.x; sf[nt][1] += p0.y;
            sf[nt][2] += p8.x; sf[nt][3] += p8.y;
            if (need_mask) {
                int lim0 = iq_g + PS, lim1 = lim0 + 8;
                if (j     > lim0) sf[nt][0] = -1e30f;
                if (j + 1 > lim0) sf[nt][1] = -1e30f;
                if (j     > lim1) sf[nt][2] = -1e30f;
                if (j + 1 > lim1) sf[nt][3] = -1e30f;
            }
        }

        // online softmax
        float tm0 = -1e30f, tm1 = -1e30f;
#pragma unroll
        for (int nt = 0; nt < 8; nt++) {
            tm0 = fmaxf(tm0, fmaxf(sf[nt][0], sf[nt][1]));
            tm1 = fmaxf(tm1, fmaxf(sf[nt][2], sf[nt][3]));
        }
        tm0 = fmaxf(tm0, __shfl_xor_sync(0xffffffffu, tm0, 1));
        tm0 = fmaxf(tm0, __shfl_xor_sync(0xffffffffu, tm0, 2));
        tm1 = fmaxf(tm1, __shfl_xor_sync(0xffffffffu, tm1, 1));
        tm1 = fmaxf(tm1, __shfl_xor_sync(0xffffffffu, tm1, 2));
        float nm0 = fmaxf(m0r, tm0), nm1 = fmaxf(m1r, tm1);
        float cr0 = __expf(m0r - nm0), cr1 = __expf(m1r - nm1);

        float ps0 = 0.f, ps1 = 0.f;
#pragma unroll
        for (int nt = 0; nt < 8; nt++) {
            float e0 = __expf(sf[nt][0] - nm0);
            float e1 = __expf(sf[nt][1] - nm0);
            float e2 = __expf(sf[nt][2] - nm1);
            float e3 = __expf(sf[nt][3] - nm1);
            Ps[pr0 + nt * 4 + t] = f22h2(e0, e1);
            Ps[pr8 + nt * 4 + t] = f22h2(e2, e3);
            ps0 += e0 + e1;
            ps1 += e2 + e3;
        }
        ps0 += __shfl_xor_sync(0xffffffffu, ps0, 1);
        ps0 += __shfl_xor_sync(0xffffffffu, ps0, 2);
        ps1 += __shfl_xor_sync(0xffffffffu, ps1, 1);
        ps1 += __shfl_xor_sync(0xffffffffu, ps1, 2);
        l0 = l0 * cr0 + ps0;
        l1 = l1 * cr1 + ps1;
        m0r = nm0; m1r = nm1;
#pragma unroll
        for (int nt = 0; nt < 8; nt++) {
            of[nt][0] *= cr0; of[nt][1] *= cr0;
            of[nt][2] *= cr1; of[nt][3] *= cr1;
        }
        __syncwarp();

        // O += P @ V  (fp16 m16n8k16, V^T tiles)
        uint32_t af[4][4];
#pragma unroll
        for (int ks2 = 0; ks2 < 4; ks2++) {
            af[ks2][0] = Ps[pr0 + ks2 * 8 + t];
            af[ks2][1] = Ps[pr8 + ks2 * 8 + t];
            af[ks2][2] = Ps[pr0 + ks2 * 8 + t + 4];
            af[ks2][3] = Ps[pr8 + ks2 * 8 + t + 4];
        }
#pragma unroll
        for (int nt = 0; nt < 8; nt++) {
#pragma unroll
            for (int ks2 = 0; ks2 < 4; ks2++) {
                uint32_t bb[2];
                bb[0] = Vc[(nt * 8 + g) * KT_LD + ks2 * 8 + t];
                bb[1] = Vc[(nt * 8 + g) * KT_LD + ks2 * 8 + t + 4];
                MMA_F16(of[nt], af[ks2], bb);
            }
        }
        __syncwarp();
    }

    float i0 = 1.f / l0, i1 = 1.f / l1;
    int orow = b * CS + q0 + w * 16 + g;
#pragma unroll
    for (int nt = 0; nt < 8; nt++) {
        int col = h * D + nt * 8 + 2 * t;
        float2 v0 = make_float2(__uint_as_float(f2tf(of[nt][0] * i0)),
                                __uint_as_float(f2tf(of[nt][1] * i0)));
        float2 v1 = make_float2(__uint_as_float(f2tf(of[nt][2] * i1)),
                                __uint_as_float(f2tf(of[nt][3] * i1)));
        *(float2*)(g_awv + (size_t)orow * HD + col) = v0;
        *(float2*)(g_awv + (size_t)(orow + 8) * HD + col) = v1;
    }
}

// ---------------- launch -------------------------------------------------------
extern "C" void kernel_launch(void* const* d_in, const int* in_sizes, int n_in,
                              void* d_out, int out_size)
{
    const float* input  = (const float*)d_in[0];
    const float* pos    = (const float*)d_in[1];
    const float* memory = (const float*)d_in[2];
    const float* u      = (const float*)d_in[3];
    const float* v      = (const float*)d_in[4];
    const float* Wkv    = (const float*)d_in[5];
    const float* Wq     = (const float*)d_in[6];
    const float* Wp     = (const float*)d_in[7];
    const float* Wout   = (const float*)d_in[8];
    float* out = (float*)d_out;

    float *pawv, *prwo;
    cudaGetSymbolAddress((void**)&pawv, g_awv);
    cudaGetSymbolAddress((void**)&prwo, r_wout);

    cudaFuncSetAttribute(mm_fused3, cudaFuncAttributeMaxDynamicSharedMemorySize, MM_SMEM);
    cudaFuncSetAttribute(mm_ca,     cudaFuncAttributeMaxDynamicSharedMemorySize, MM_SMEM);
    cudaFuncSetAttribute(mm_pa2,    cudaFuncAttributeMaxDynamicSharedMemorySize, PA_SMEM);
    cudaFuncSetAttribute(attn_tc,   cudaFuncAttributeMaxDynamicSharedMemorySize, ATT_SMEM);

    // launch 0: fused tf32 pre-round of all sources + pa zero-cell fixup
    prep<<<15616, 256>>>(input, memory, pos, Wkv, Wq, Wp, Wout);
    // launch 1: fused kv + q + p GEMMs (kv stores K fp16 + V^T fp16)
    mm_fused3<<<1408, 256, MM_SMEM>>>();
    // launch 2: pos-attn per head, shift-on-write
    mm_pa2<<<dim3(16, 32, H), 256, PA_SMEM>>>(v);
    // launch 3: flash attention (fp16 m16n8k16)
    attn_tc<<<dim3(8, H, BSZ), 256, ATT_SMEM>>>(u);
    // launch 4: out = awv @ W_out
    mm_ca<<<dim3(8, 32), 256, MM_SMEM>>>(pawv, prwo, out, BSZ * CS, DIN, HD);
}

// round 17
// speedup vs baseline: 1.5786x; 1.2458x over previous
#include <cuda_runtime.h>
#include <cuda_fp16.h>
#include <cstdint>

#define BSZ 4
#define CS  1024
#define PS  1024
#define DIN 1024
#define H   16
#define D   64
#define T   2048
#define HD  (H * D)
#define SCALEF 0.125f

// ---------------- scratch (static device globals; allocation-free) ----------
__device__ __half g_k16[(size_t)BSZ * T * HD];      // [b*T+t][dim] fp16 keys
__device__ __half g_vT [(size_t)BSZ * HD * T];      // [b][dim][t]  fp16 values (transposed)
__device__ float  g_q  [(size_t)BSZ * CS * HD];     // fp32 (full GEMM precision)
__device__ float  g_p  [(size_t)T * HD];
__device__ float  g_pa [(size_t)H * BSZ * CS * T];  // [h][M][j] SHIFTED+SCALED position scores
__device__ __half g_awv16[(size_t)BSZ * CS * HD];   // fp16 attention output

// fp16 copies of GEMM sources
__device__ __half rh_input[(size_t)BSZ * CS * DIN];
__device__ __half rh_mem  [(size_t)BSZ * PS * DIN];
__device__ __half rh_pos  [(size_t)T * DIN];
__device__ __half wkvT[(size_t)2 * HD * DIN];       // [n=2048][k=1024]
__device__ __half wqT [(size_t)HD * DIN];           // [n][k]
__device__ __half wpT [(size_t)HD * DIN];
__device__ __half woT [(size_t)DIN * HD];           // [n=1024][k=1024]

// ---------------- helpers ----------------------------------------------------
__device__ __forceinline__ uint32_t f22h2(float lo, float hi) {
    __half2 h = __floats2half2_rn(lo, hi);
    return *(uint32_t*)&h;
}

#define MMA_F16(c, a, b) \
    asm volatile("mma.sync.aligned.m16n8k16.row.col.f32.f16.f16.f32 " \
                 "{%0,%1,%2,%3},{%4,%5,%6,%7},{%8,%9},{%0,%1,%2,%3};" \
                 : "+f"(c[0]), "+f"(c[1]), "+f"(c[2]), "+f"(c[3]) \
                 : "r"(a[0]), "r"(a[1]), "r"(a[2]), "r"(a[3]), "r"(b[0]), "r"(b[1]))

__device__ __forceinline__ void cp16(uint32_t* smem_dst, const void* gmem_src) {
    uint32_t sa = (uint32_t)__cvta_generic_to_shared(smem_dst);
    asm volatile("cp.async.cg.shared.global [%0], [%1], 16;" :: "r"(sa), "l"(gmem_src));
}
#define CP_COMMIT asm volatile("cp.async.commit_group;")
#define CP_WAIT1  asm volatile("cp.async.wait_group 1;")
#define CP_WAIT0  asm volatile("cp.async.wait_group 0;")

// ---------------- prep: fp16 conversion of inputs + pa zero fixup ------------
__device__ __forceinline__ void r4h(__half* dst, const float* src, int i) {
    float4 v = *(const float4*)(src + (size_t)i * 4);
    uint2 r;
    r.x = f22h2(v.x, v.y);
    r.y = f22h2(v.z, v.w);
    *(uint2*)(dst + (size_t)i * 4) = r;
}

__global__ void prep2(const float* __restrict__ in_, const float* __restrict__ mem_,
                      const float* __restrict__ pos_)
{
    int i = blockIdx.x * 256 + threadIdx.x;
    const int N1 = 1048576, N2 = 524288;
    if (i < N1) { r4h(rh_input, in_, i); return; }  i -= N1;
    if (i < N1) { r4h(rh_mem,   mem_, i); return; } i -= N1;
    if (i < N2) { r4h(rh_pos,   pos_, i); return; } i -= N2;
    // pa zero-cell fixup: sp=2049 -> j=M-2047 (2047<=M<=4094); sp=4098 -> j=M+2 (M<=2045)
    if (i < H * 4096) {
        int h = i >> 12, M = i & 4095;
        int j = -1;
        if (M >= 2047) { if (M <= 4094) j = M - 2047; }
        else if (M < 2046) j = M + 2;
        if (j >= 0) g_pa[((size_t)h * (BSZ * CS) + M) * T + j] = 0.f;
    }
}

// fused transpose+convert of the four weights into half [n][k]
__global__ void tpose(const float* __restrict__ wkv, const float* __restrict__ wq,
                      const float* __restrict__ wp, const float* __restrict__ wo)
{
    __shared__ float tile[32][33];
    int bid = blockIdx.x;
    const float* src; __half* dst; int R, C, local;
    if (bid < 2048)      { src = wkv; dst = wkvT; R = DIN; C = 2 * HD; local = bid; }
    else if (bid < 3072) { src = wq;  dst = wqT;  R = DIN; C = HD;     local = bid - 2048; }
    else if (bid < 4096) { src = wp;  dst = wpT;  R = DIN; C = HD;     local = bid - 3072; }
    else                 { src = wo;  dst = woT;  R = HD;  C = DIN;    local = bid - 4096; }
    int nct = C >> 5;
    int c0 = (local % nct) * 32, r0 = (local / nct) * 32;
    int tx = threadIdx.x, ty = threadIdx.y;
#pragma unroll
    for (int i = ty; i < 32; i += 8)
        tile[i][tx] = src[(size_t)(r0 + i) * C + c0 + tx];
    __syncthreads();
#pragma unroll
    for (int i = ty; i < 32; i += 8)
        dst[(size_t)(c0 + i) * R + r0 + tx] = __float2half_rn(tile[tx][i]);
}

// ---------------- fp16 GEMM core (128x128 tiles, K-chunk 32, 2-stage) --------
#define HA_LD 20                         // 16 u32 data + 4 pad per 32-half row
#define HSTG  (2 * 128 * HA_LD)          // A+B per stage (u32)
#define HMM_SMEM (2 * HSTG * 4)          // 40960 B

__device__ __forceinline__ void mma_chunk16(float acc[4][4][4],
                                            const uint32_t* __restrict__ As,
                                            const uint32_t* __restrict__ Bs,
                                            int wm, int wn, int lane)
{
    int g = lane >> 2, t = lane & 3;
#pragma unroll
    for (int ks2 = 0; ks2 < 2; ks2++) {
        int col = ks2 * 8 + t;
        uint32_t a[4][4];
#pragma unroll
        for (int mt = 0; mt < 4; mt++) {
            int row = wm * 64 + mt * 16 + g;
            a[mt][0] = As[row * HA_LD + col];
            a[mt][1] = As[(row + 8) * HA_LD + col];
            a[mt][2] = As[row * HA_LD + col + 4];
            a[mt][3] = As[(row + 8) * HA_LD + col + 4];
        }
        uint32_t b[4][2];
#pragma unroll
        for (int nt = 0; nt < 4; nt++) {
            int n = wn * 32 + nt * 8 + g;
            b[nt][0] = Bs[n * HA_LD + col];
            b[nt][1] = Bs[n * HA_LD + col + 4];
        }
#pragma unroll
        for (int mt = 0; mt < 4; mt++)
#pragma unroll
            for (int nt = 0; nt < 4; nt++)
                MMA_F16(acc[mt][nt], a[mt], b[nt]);
    }
}

__device__ __forceinline__ void store_Cr(float acc[4][4][4], float* C, int ldc,
                                         int m0, int n0, int wm, int wn, int lane)
{
    int g = lane >> 2, t = lane & 3;
#pragma unroll
    for (int mt = 0; mt < 4; mt++) {
#pragma unroll
        for (int nt = 0; nt < 4; nt++) {
            int row = m0 + wm * 64 + mt * 16 + g;
            int col = n0 + wn * 32 + nt * 8 + 2 * t;
            *(float2*)(C + (size_t)row * ldc + col) =
                make_float2(acc[mt][nt][0], acc[mt][nt][1]);
            *(float2*)(C + (size_t)(row + 8) * ldc + col) =
                make_float2(acc[mt][nt][2], acc[mt][nt][3]);
        }
    }
}

// kv epilogue: K half rows to g_k16, V half transposed to g_vT
__device__ __forceinline__ void store_kv_half(float acc[4][4][4], int m0, int n0,
                                              int wm, int wn, int lane)
{
    int g = lane >> 2, t = lane & 3;
#pragma unroll
    for (int mt = 0; mt < 4; mt++) {
#pragma unroll
        for (int nt = 0; nt < 4; nt++) {
            int row = m0 + wm * 64 + mt * 16 + g;
            int col = n0 + wn * 32 + nt * 8 + 2 * t;
            float v0 = acc[mt][nt][0], v1 = acc[mt][nt][1];
            float v2 = acc[mt][nt][2], v3 = acc[mt][nt][3];
            if (col < 1024) {
                *(uint32_t*)(g_k16 + (size_t)row * HD + col)       = f22h2(v0, v1);
                *(uint32_t*)(g_k16 + (size_t)(row + 8) * HD + col) = f22h2(v2, v3);
            } else {
                int d = col - 1024;
                int bb = row >> 11, tr = row & (T - 1);
                __half* vb = g_vT + (size_t)bb * HD * T;
                vb[(size_t)d * T + tr]           = __float2half_rn(v0);
                vb[(size_t)(d + 1) * T + tr]     = __float2half_rn(v1);
                vb[(size_t)d * T + tr + 8]       = __float2half_rn(v2);
                vb[(size_t)(d + 1) * T + tr + 8] = __float2half_rn(v3);
            }
        }
    }
}

// stage A (mode 0: kv-gathered, else plain rows, lda=DIN halves) 128x32 halves
__device__ __forceinline__ void stage_hA(uint32_t* As, int mode,
                                         const __half* __restrict__ A,
                                         int m0, int k0, int tid)
{
#pragma unroll
    for (int i = 0; i < 2; i++) {
        int s = tid + i * 256;
        int row = s >> 2, q = s & 3;
        const __half* src;
        if (mode == 0) {
            int grow = m0 + row;
            int b = grow >> 11, tl = grow & (T - 1);
            src = (tl < PS) ? (rh_mem + (size_t)(b * PS + tl) * DIN)
                            : (rh_input + (size_t)(b * CS + tl - PS) * DIN);
        } else {
            src = A + (size_t)(m0 + row) * DIN;
        }
        cp16(&As[row * HA_LD + q * 4], src + k0 + q * 8);
    }
}
// stage B: Bt half [n][K] rows
__device__ __forceinline__ void stage_hB(uint32_t* Bs, const __half* __restrict__ Bt,
                                         int ldk, int n0, int k0, int tid)
{
#pragma unroll
    for (int i = 0; i < 2; i++) {
        int s = tid + i * 256;
        int row = s >> 2, q = s & 3;
        cp16(&Bs[row * HA_LD + q * 4], Bt + (size_t)(n0 + row) * ldk + k0 + q * 8);
    }
}

// fused kv + q + p GEMM: 1408 blocks
__global__ __launch_bounds__(256, 2)
void mm_f16_fused()
{
    extern __shared__ uint32_t dsm[];
    int tid = threadIdx.x, lane = tid & 31, w = tid >> 5;
    int wm = w >> 2, wn = w & 3;

    int bid = blockIdx.x;
    int mode, m0, n0;
    const __half *A = nullptr, *Bt;
    float* C = nullptr;
    if (bid < 1024) {            // kv: 64 x 16 tiles
        mode = 0; m0 = (bid >> 4) * 128; n0 = (bid & 15) * 128;
        Bt = wkvT;
    } else if (bid < 1280) {     // q: 32 x 8 tiles
        int i = bid - 1024;
        mode = 1; m0 = (i >> 3) * 128; n0 = (i & 7) * 128;
        A = rh_input; Bt = wqT; C = g_q;
    } else {                     // p: 16 x 8 tiles
        int i = bid - 1280;
        mode = 2; m0 = (i >> 3) * 128; n0 = (i & 7) * 128;
        A = rh_pos; Bt = wpT; C = g_p;
    }

    float acc[4][4][4];
#pragma unroll
    for (int i = 0; i < 4; i++)
#pragma unroll
        for (int j = 0; j < 4; j++)
#pragma unroll
            for (int r = 0; r < 4; r++) acc[i][j][r] = 0.f;

    uint32_t* SA[2] = { dsm, dsm + HSTG };
    uint32_t* SB[2] = { dsm + 128 * HA_LD, dsm + HSTG + 128 * HA_LD };

    stage_hA(SA[0], mode, A, m0, 0, tid);  stage_hB(SB[0], Bt, DIN, n0, 0, tid);  CP_COMMIT;
    stage_hA(SA[1], mode, A, m0, 32, tid); stage_hB(SB[1], Bt, DIN, n0, 32, tid); CP_COMMIT;
    CP_WAIT1;
    __syncthreads();

    const int NK = DIN >> 5;
    for (int k = 0; k < NK; k++) {
        int cur = k & 1;
        mma_chunk16(acc, SA[cur], SB[cur], wm, wn, lane);
        __syncthreads();
        if (k + 2 < NK) {
            stage_hA(SA[cur], mode, A, m0, (k + 2) * 32, tid);
            stage_hB(SB[cur], Bt, DIN, n0, (k + 2) * 32, tid);
        }
        CP_COMMIT;
        CP_WAIT1;
        __syncthreads();
    }
    if (mode == 0) store_kv_half(acc, m0, n0, wm, wn, lane);
    else           store_Cr(acc, C, HD, m0, n0, wm, wn, lane);
}

// out GEMM: out = awv16 @ woT^T   (4096 x 1024 x 1024)
__global__ __launch_bounds__(256, 2)
void mm_out16(float* __restrict__ C)
{
    extern __shared__ uint32_t dsm[];
    int tid = threadIdx.x, lane = tid & 31, w = tid >> 5;
    int wm = w >> 2, wn = w & 3;
    int m0 = blockIdx.y * 128, n0 = blockIdx.x * 128;

    float acc[4][4][4];
#pragma unroll
    for (int i = 0; i < 4; i++)
#pragma unroll
        for (int j = 0; j < 4; j++)
#pragma unroll
            for (int r = 0; r < 4; r++) acc[i][j][r] = 0.f;

    uint32_t* SA[2] = { dsm, dsm + HSTG };
    uint32_t* SB[2] = { dsm + 128 * HA_LD, dsm + HSTG + 128 * HA_LD };

    stage_hA(SA[0], 1, g_awv16, m0, 0, tid);  stage_hB(SB[0], woT, DIN, n0, 0, tid);  CP_COMMIT;
    stage_hA(SA[1], 1, g_awv16, m0, 32, tid); stage_hB(SB[1], woT, DIN, n0, 32, tid); CP_COMMIT;
    CP_WAIT1;
    __syncthreads();

    const int NK = DIN >> 5;
    for (int k = 0; k < NK; k++) {
        int cur = k & 1;
        mma_chunk16(acc, SA[cur], SB[cur], wm, wn, lane);
        __syncthreads();
        if (k + 2 < NK) {
            stage_hA(SA[cur], 1, g_awv16, m0, (k + 2) * 32, tid);
            stage_hB(SB[cur], woT, DIN, n0, (k + 2) * 32, tid);
        }
        CP_COMMIT;
        CP_WAIT1;
        __syncthreads();
    }
    store_Cr(acc, C, DIN, m0, n0, wm, wn, lane);
}

// ---------------- position-attn fp16 GEMM with SHIFT-ON-WRITE epilogue -------
#define PA_LD 36                           // 32 u32 data (64 halves) + 4 pad
#define PA_SMEM (2 * 128 * PA_LD * 4)      // 36864 B

__device__ __forceinline__ void scatter_pa(float* __restrict__ Ch, int rp, int cp, float val)
{
    int s = rp + cp;
    int a = (s <= 2046) ? 2 : ((s <= 4094) ? 1 : 0);
    int M = rp - a;
    if (M < 0) return;
    int j = s + 1 - 4096 + (a << 11);
    if (j > (M & (CS - 1)) + PS) return;   // masked cell — overwritten by -1e30 at read
    Ch[(size_t)M * T + j] = val * SCALEF;
}

__global__ __launch_bounds__(256, 2)
void mm_pa16(const float* __restrict__ vvec)
{
    extern __shared__ uint32_t psm[];
    uint32_t* As = psm;                    // 128 x PA_LD (q+v halves, k-major)
    uint32_t* Bs = psm + 128 * PA_LD;      // 128 x PA_LD (p rows)

    int tid = threadIdx.x, lane = tid & 31, w = tid >> 5;
    int wm = w >> 2, wn = w & 3;
    int h = blockIdx.z;
    int m0 = blockIdx.y * 128, n0 = blockIdx.x * 128;
    int g = lane >> 2, t = lane & 3;

#pragma unroll
    for (int l = 0; l < 4; l++) {
        int idx = tid + l * 256;
        int r = idx >> 3, qq = idx & 7;    // 8 halves per item
        const float* qa = g_q + (size_t)(m0 + r) * HD + h * D + qq * 8;
        const float* vv = vvec + h * D + qq * 8;
        float4 a0 = *(const float4*)qa, a1 = *(const float4*)(qa + 4);
        float4 v0 = *(const float4*)vv, v1 = *(const float4*)(vv + 4);
        uint4 ua;
        ua.x = f22h2(a0.x + v0.x, a0.y + v0.y);
        ua.y = f22h2(a0.z + v0.z, a0.w + v0.w);
        ua.z = f22h2(a1.x + v1.x, a1.y + v1.y);
        ua.w = f22h2(a1.z + v1.z, a1.w + v1.w);
        *(uint4*)&As[r * PA_LD + qq * 4] = ua;
        const float* pp = g_p + (size_t)(n0 + r) * HD + h * D + qq * 8;
        float4 p0 = *(const float4*)pp, p1 = *(const float4*)(pp + 4);
        uint4 ub;
        ub.x = f22h2(p0.x, p0.y); ub.y = f22h2(p0.z, p0.w);
        ub.z = f22h2(p1.x, p1.y); ub.w = f22h2(p1.z, p1.w);
        *(uint4*)&Bs[r * PA_LD + qq * 4] = ub;
    }
    __syncthreads();

    float acc[4][4][4];
#pragma unroll
    for (int i = 0; i < 4; i++)
#pragma unroll
        for (int j = 0; j < 4; j++)
#pragma unroll
            for (int r = 0; r < 4; r++) acc[i][j][r] = 0.f;

#pragma unroll
    for (int ks2 = 0; ks2 < 4; ks2++) {
        int col = ks2 * 8 + t;
        uint32_t a[4][4];
#pragma unroll
        for (int mt = 0; mt < 4; mt++) {
            int row = wm * 64 + mt * 16 + g;
            a[mt][0] = As[row * PA_LD + col];
            a[mt][1] = As[(row + 8) * PA_LD + col];
            a[mt][2] = As[row * PA_LD + col + 4];
            a[mt][3] = As[(row + 8) * PA_LD + col + 4];
        }
        uint32_t b[4][2];
#pragma unroll
        for (int nt = 0; nt < 4; nt++) {
            int n = wn * 32 + nt * 8 + g;
            b[nt][0] = Bs[n * PA_LD + col];
            b[nt][1] = Bs[n * PA_LD + col + 4];
        }
#pragma unroll
        for (int mt = 0; mt < 4; mt++)
#pragma unroll
            for (int nt = 0; nt < 4; nt++)
                MMA_F16(acc[mt][nt], a[mt], b[nt]);
    }

    float* Ch = g_pa + (size_t)h * (BSZ * CS) * T;
#pragma unroll
    for (int mt = 0; mt < 4; mt++) {
#pragma unroll
        for (int nt = 0; nt < 4; nt++) {
            int row0 = m0 + wm * 64 + mt * 16 + g;
            int col0 = n0 + wn * 32 + nt * 8 + 2 * t;
            scatter_pa(Ch, row0,     col0,     acc[mt][nt][0]);
            scatter_pa(Ch, row0,     col0 + 1, acc[mt][nt][1]);
            scatter_pa(Ch, row0 + 8, col0,     acc[mt][nt][2]);
            scatter_pa(Ch, row0 + 8, col0 + 1, acc[mt][nt][3]);
        }
    }
}

// ---------------- flash attention: fp16 m16n8k16 pipeline ---------------------
#define KT_LD 36                                     // 32 half2 + 4 pad per row
#define ATT_SMEM ((4 * 64 * KT_LD + 128 * KT_LD) * 4)   // 55296 B

__device__ __forceinline__ void stage_kv16(uint32_t* kbuf, uint32_t* vbuf,
                                           int b, int h, int j0, int tid)
{
#pragma unroll
    for (int l = 0; l < 2; l++) {
        int idx = tid + l * 256;
        int r = idx >> 3, q = idx & 7;
        cp16(kbuf + r * KT_LD + q * 4,
             g_k16 + (size_t)(b * T + j0 + r) * HD + h * D + q * 8);
    }
#pragma unroll
    for (int l = 0; l < 2; l++) {
        int idx = tid + l * 256;
        int r = idx >> 3, q = idx & 7;
        cp16(vbuf + r * KT_LD + q * 4,
             g_vT + ((size_t)b * HD + h * D + r) * T + j0 + q * 8);
    }
}

__global__ __launch_bounds__(256, 2)
void attn_tc(const float* __restrict__ u)
{
    extern __shared__ uint32_t sm[];
    uint32_t* Ps = sm + 4 * 64 * KT_LD;   // 128 x KT_LD (Q staging as half2, then P)

    int tid = threadIdx.x, lane = tid & 31, w = tid >> 5;
    int b = blockIdx.z, h = blockIdx.y;
    int q0 = (int)(gridDim.x - 1 - blockIdx.x) * 128;
    int g = lane >> 2, t = lane & 3;

    // Q(+u)*SCALE as half2
    for (int i = tid; i < 128 * 16; i += 256) {
        int r = i >> 4, c = i & 15;
        float4 qv = *(const float4*)(g_q + (size_t)(b * CS + q0 + r) * HD + h * D + c * 4);
        float4 uv = *(const float4*)(u + h * D + c * 4);
        Ps[r * KT_LD + c * 2]     = f22h2((qv.x + uv.x) * SCALEF, (qv.y + uv.y) * SCALEF);
        Ps[r * KT_LD + c * 2 + 1] = f22h2((qv.z + uv.z) * SCALEF, (qv.w + uv.w) * SCALEF);
    }
    __syncthreads();

    uint32_t qf[4][4];
    {
        int r0 = w * 16 + g;
#pragma unroll
        for (int ks2 = 0; ks2 < 4; ks2++) {
            qf[ks2][0] = Ps[r0 * KT_LD + ks2 * 8 + t];
            qf[ks2][1] = Ps[(r0 + 8) * KT_LD + ks2 * 8 + t];
            qf[ks2][2] = Ps[r0 * KT_LD + ks2 * 8 + t + 4];
            qf[ks2][3] = Ps[(r0 + 8) * KT_LD + ks2 * 8 + t + 4];
        }
    }

    float of[8][4];
#pragma unroll
    for (int nt = 0; nt < 8; nt++)
#pragma unroll
        for (int r = 0; r < 4; r++) of[nt][r] = 0.f;
    float m0r = -1e30f, m1r = -1e30f, l0 = 0.f, l1 = 0.f;

    int iq_g = q0 + w * 16 + g;
    int Mrow_g = b * CS + iq_g;
    int pr0 = (w * 16 + g) * KT_LD, pr8 = pr0 + 8 * KT_LD;
    int ntiles = q0 / 64 + 18;

    const float* pab0 = g_pa + ((size_t)h * (BSZ * CS) + Mrow_g) * T;
    const float* pab8 = pab0 + (size_t)8 * T;

    stage_kv16(sm, sm + 2 * 64 * KT_LD, b, h, 0, tid);
    CP_COMMIT;

    for (int tt = 0; tt < ntiles; tt++) {
        int cur = tt & 1;
        uint32_t* Kc = sm + cur * (64 * KT_LD);
        uint32_t* Vc = sm + 2 * 64 * KT_LD + cur * (64 * KT_LD);
        int j0 = tt * 64;

        __syncthreads();
        if (tt + 1 < ntiles) {
            stage_kv16(sm + (1 - cur) * (64 * KT_LD),
                       sm + 2 * 64 * KT_LD + (1 - cur) * (64 * KT_LD), b, h, j0 + 64, tid);
            CP_COMMIT;
            CP_WAIT1;
        } else {
            CP_WAIT0;
        }
        __syncthreads();

        // S = (Q+u)*SCALE @ K^T  (fp16 m16n8k16)
        float sf[8][4];
#pragma unroll
        for (int nt = 0; nt < 8; nt++) {
            sf[nt][0] = sf[nt][1] = sf[nt][2] = sf[nt][3] = 0.f;
#pragma unroll
            for (int ks2 = 0; ks2 < 4; ks2++) {
                uint32_t bb[2];
                bb[0] = Kc[(nt * 8 + g) * KT_LD + ks2 * 8 + t];
                bb[1] = Kc[(nt * 8 + g) * KT_LD + ks2 * 8 + t + 4];
                MMA_F16(sf[nt], qf[ks2], bb);
            }
        }

        // add pre-shifted pre-scaled pos + mask
        bool need_mask = (tt >= ntiles - 2);
#pragma unroll
        for (int nt = 0; nt < 8; nt++) {
            int j = j0 + nt * 8 + 2 * t;
            float2 p0 = __ldg((const float2*)(pab0 + j));
            float2 p8 = __ldg((const float2*)(pab8 + j));
            sf[nt][0] += p0.x; sf[nt][1] += p0.y;
            sf[nt][2] += p8.x; sf[nt][3] += p8.y;
            if (need_mask) {
                int lim0 = iq_g + PS, lim1 = lim0 + 8;
                if (j     > lim0) sf[nt][0] = -1e30f;
                if (j + 1 > lim0) sf[nt][1] = -1e30f;
                if (j     > lim1) sf[nt][2] = -1e30f;
                if (j + 1 > lim1) sf[nt][3] = -1e30f;
            }
        }

        // online softmax
        float tm0 = -1e30f, tm1 = -1e30f;
#pragma unroll
        for (int nt = 0; nt < 8; nt++) {
            tm0 = fmaxf(tm0, fmaxf(sf[nt][0], sf[nt][1]));
            tm1 = fmaxf(tm1, fmaxf(sf[nt][2], sf[nt][3]));
        }
        tm0 = fmaxf(tm0, __shfl_xor_sync(0xffffffffu, tm0, 1));
        tm0 = fmaxf(tm0, __shfl_xor_sync(0xffffffffu, tm0, 2));
        tm1 = fmaxf(tm1, __shfl_xor_sync(0xffffffffu, tm1, 1));
        tm1 = fmaxf(tm1, __shfl_xor_sync(0xffffffffu, tm1, 2));
        float nm0 = fmaxf(m0r, tm0), nm1 = fmaxf(m1r, tm1);
        float cr0 = __expf(m0r - nm0), cr1 = __expf(m1r - nm1);

        float ps0 = 0.f, ps1 = 0.f;
#pragma unroll
        for (int nt = 0; nt < 8; nt++) {
            float e0 = __expf(sf[nt][0] - nm0);
            float e1 = __expf(sf[nt][1] - nm0);
            float e2 = __expf(sf[nt][2] - nm1);
            float e3 = __expf(sf[nt][3] - nm1);
            Ps[pr0 + nt * 4 + t] = f22h2(e0, e1);
            Ps[pr8 + nt * 4 + t] = f22h2(e2, e3);
            ps0 += e0 + e1;
            ps1 += e2 + e3;
        }
        ps0 += __shfl_xor_sync(0xffffffffu, ps0, 1);
        ps0 += __shfl_xor_sync(0xffffffffu, ps0, 2);
        ps1 += __shfl_xor_sync(0xffffffffu, ps1, 1);
        ps1 += __shfl_xor_sync(0xffffffffu, ps1, 2);
        l0 = l0 * cr0 + ps0;
        l1 = l1 * cr1 + ps1;
        m0r = nm0; m1r = nm1;
#pragma unroll
        for (int nt = 0; nt < 8; nt++) {
            of[nt][0] *= cr0; of[nt][1] *= cr0;
            of[nt][2] *= cr1; of[nt][3] *= cr1;
        }
        __syncwarp();

        // O += P @ V  (fp16 m16n8k16, V^T tiles)
        uint32_t af[4][4];
#pragma unroll
        for (int ks2 = 0; ks2 < 4; ks2++) {
            af[ks2][0] = Ps[pr0 + ks2 * 8 + t];
            af[ks2][1] = Ps[pr8 + ks2 * 8 + t];
            af[ks2][2] = Ps[pr0 + ks2 * 8 + t + 4];
            af[ks2][3] = Ps[pr8 + ks2 * 8 + t + 4];
        }
#pragma unroll
        for (int nt = 0; nt < 8; nt++) {
#pragma unroll
            for (int ks2 = 0; ks2 < 4; ks2++) {
                uint32_t bb[2];
                bb[0] = Vc[(nt * 8 + g) * KT_LD + ks2 * 8 + t];
                bb[1] = Vc[(nt * 8 + g) * KT_LD + ks2 * 8 + t + 4];
                MMA_F16(of[nt], af[ks2], bb);
            }
        }
        __syncwarp();
    }

    float i0 = 1.f / l0, i1 = 1.f / l1;
    int orow = b * CS + q0 + w * 16 + g;
#pragma unroll
    for (int nt = 0; nt < 8; nt++) {
        int col = h * D + nt * 8 + 2 * t;
        *(uint32_t*)(g_awv16 + (size_t)orow * HD + col) =
            f22h2(of[nt][0] * i0, of[nt][1] * i0);
        *(uint32_t*)(g_awv16 + (size_t)(orow + 8) * HD + col) =
            f22h2(of[nt][2] * i1, of[nt][3] * i1);
    }
}

// ---------------- launch -------------------------------------------------------
extern "C" void kernel_launch(void* const* d_in, const int* in_sizes, int n_in,
                              void* d_out, int out_size)
{
    const float* input  = (const float*)d_in[0];
    const float* pos    = (const float*)d_in[1];
    const float* memory = (const float*)d_in[2];
    const float* u      = (const float*)d_in[3];
    const float* v      = (const float*)d_in[4];
    const float* Wkv    = (const float*)d_in[5];
    const float* Wq     = (const float*)d_in[6];
    const float* Wp     = (const float*)d_in[7];
    const float* Wout   = (const float*)d_in[8];
    float* out = (float*)d_out;

    cudaFuncSetAttribute(mm_f16_fused, cudaFuncAttributeMaxDynamicSharedMemorySize, HMM_SMEM);
    cudaFuncSetAttribute(mm_out16,     cudaFuncAttributeMaxDynamicSharedMemorySize, HMM_SMEM);
    cudaFuncSetAttribute(mm_pa16,      cudaFuncAttributeMaxDynamicSharedMemorySize, PA_SMEM);
    cudaFuncSetAttribute(attn_tc,      cudaFuncAttributeMaxDynamicSharedMemorySize, ATT_SMEM);

    // launch 0: fp16 conversion of inputs + pa zero-cell fixup
    prep2<<<10496, 256>>>(input, memory, pos);
    // launch 1: fused transpose+convert of the 4 weights to half [n][k]
    tpose<<<5120, dim3(32, 8)>>>(Wkv, Wq, Wp, Wout);
    // launch 2: fused kv + q + p fp16 GEMMs (kv stores K fp16 + V^T fp16)
    mm_f16_fused<<<1408, 256, HMM_SMEM>>>();
    // launch 3: pos-attn fp16 GEMM, shift-on-write
    mm_pa16<<<dim3(16, 32, H), 256, PA_SMEM>>>(v);
    // launch 4: flash attention (fp16 m16n8k16)
    attn_tc<<<dim3(8, H, BSZ), 256, ATT_SMEM>>>(u);
    // launch 5: out = awv @ W_out (fp16 GEMM, fp32 store)
    mm_out16<<<dim3(8, 32), 256, HMM_SMEM>>>(out);
}